// round 1
// baseline (speedup 1.0000x reference)
#include <cuda_runtime.h>
#include <cuda_bf16.h>

// ---------------- problem constants ----------------
#define L     3072
#define NTOK  3071
#define Dm    512
#define Hh    8
#define DHd   64
#define FFd   512
#define T_TYPES 15
#define N_ARGS  73
#define N_MAPS  3

// ---------------- scratch (static device globals; no allocations) ----------------
__device__ float g_x [L * Dm];
__device__ float g_q [L * Dm];
__device__ float g_k [L * Dm];
__device__ float g_v [L * Dm];
__device__ float g_o [L * Dm];
__device__ float g_a [L * Dm];
__device__ float g_xa[L * Dm];
__device__ float g_h [L * FFd];
__device__ float g_y [L * Dm];
__device__ int   g_seg[L];

// ---------------- embedding: x[0]=sos, x[1+n] = Wt[:,t]+bt + Wa[:,a]+ba + Wm[:,m]+bm ----------------
__global__ void embed_kernel(const int* __restrict__ idx,
                             const float* __restrict__ Wt, const float* __restrict__ bt,
                             const float* __restrict__ Wa, const float* __restrict__ ba,
                             const float* __restrict__ Wm, const float* __restrict__ bm,
                             const float* __restrict__ sos,
                             float* __restrict__ X) {
    int g = blockIdx.x * blockDim.x + threadIdx.x;
    if (g >= L * Dm) return;
    int n = g >> 9;          // g / 512
    int d = g & 511;         // g % 512
    if (n == 0) { X[g] = sos[d]; return; }
    int id = idx[n - 1];
    int t = id / (N_ARGS * N_MAPS);
    int a = (id / N_MAPS) % N_ARGS;
    int m = id % N_MAPS;
    X[g] = Wt[d * T_TYPES + t] + bt[d]
         + Wa[d * N_ARGS + a] + ba[d]
         + Wm[d * N_MAPS + m] + bm[d];
}

// ---------------- scan: batch ids (cumsum of seq_masks==0) -> per-row segment start ----------------
// bid[0] = -1, bid[i] = #zeros in seq_masks[0..i-1].  Row i attends {0} U [seg[i], i-1].
__global__ void scan_kernel(const int* __restrict__ seq, int* __restrict__ segOut) {
    __shared__ int sA[L];
    __shared__ int sB[L];
    int tid = threadIdx.x;
    for (int i = tid; i < L; i += 1024)
        sA[i] = (i < NTOK && seq[i] == 0) ? 1 : 0;
    __syncthreads();
    int* src = sA; int* dst = sB;
    // inclusive +scan (Hillis-Steele)
    for (int d = 1; d < L; d <<= 1) {
        for (int i = tid; i < L; i += 1024)
            dst[i] = src[i] + (i >= d ? src[i - d] : 0);
        __syncthreads();
        int* t = src; src = dst; dst = t;
    }
    // bid into dst
    for (int i = tid; i < L; i += 1024)
        dst[i] = (i == 0) ? -1 : src[i - 1];
    __syncthreads();
    // boundary value into src: val[i] = i if (i>=1 && (i==1 || bid[i]!=bid[i-1])) else 0
    for (int i = tid; i < L; i += 1024) {
        int val = 0;
        if (i >= 1 && (i == 1 || dst[i] != dst[i - 1])) val = i;
        src[i] = val;
    }
    __syncthreads();
    // inclusive max-scan
    for (int d = 1; d < L; d <<= 1) {
        for (int i = tid; i < L; i += 1024)
            dst[i] = max(src[i], (i >= d ? src[i - d] : 0));
        __syncthreads();
        int* t = src; src = dst; dst = t;
    }
    for (int i = tid; i < L; i += 1024)
        segOut[i] = src[i];
}

// ---------------- SGEMM: C[M,N] = A[M,K] @ W[N,K]^T + bias, optional leaky_relu ----------------
// All GEMMs here are M=3072, N=512, K=512.
#define BM 64
#define BN 64
#define BK 16
__global__ __launch_bounds__(256) void gemm_kernel(
    const float* __restrict__ A, const float* __restrict__ W,
    const float* __restrict__ bias, float* __restrict__ C, int act) {
    __shared__ float As[BK][BM + 4];
    __shared__ float Bs[BK][BN + 4];
    const int bm = blockIdx.y * BM;
    const int bn = blockIdx.x * BN;
    const int tid = threadIdx.x;
    const int tm = (tid >> 4) << 2;     // 0..60 step 4 (row within tile)
    const int tn = (tid & 15) << 2;     // 0..60 step 4 (col within tile)
    const int lr = tid >> 2;            // 0..63
    const int lc = (tid & 3) << 2;      // 0,4,8,12

    float acc[4][4] = {};
    const float* Ap = A + (size_t)(bm + lr) * Dm + lc;
    const float* Wp = W + (size_t)(bn + lr) * Dm + lc;

    for (int k0 = 0; k0 < Dm; k0 += BK) {
        float4 a4 = *(const float4*)(Ap + k0);
        float4 b4 = *(const float4*)(Wp + k0);
        As[lc + 0][lr] = a4.x; As[lc + 1][lr] = a4.y;
        As[lc + 2][lr] = a4.z; As[lc + 3][lr] = a4.w;
        Bs[lc + 0][lr] = b4.x; Bs[lc + 1][lr] = b4.y;
        Bs[lc + 2][lr] = b4.z; Bs[lc + 3][lr] = b4.w;
        __syncthreads();
#pragma unroll
        for (int k = 0; k < BK; ++k) {
            float4 av = *(const float4*)&As[k][tm];
            float4 bv = *(const float4*)&Bs[k][tn];
            acc[0][0] += av.x * bv.x; acc[0][1] += av.x * bv.y;
            acc[0][2] += av.x * bv.z; acc[0][3] += av.x * bv.w;
            acc[1][0] += av.y * bv.x; acc[1][1] += av.y * bv.y;
            acc[1][2] += av.y * bv.z; acc[1][3] += av.y * bv.w;
            acc[2][0] += av.z * bv.x; acc[2][1] += av.z * bv.y;
            acc[2][2] += av.z * bv.z; acc[2][3] += av.z * bv.w;
            acc[3][0] += av.w * bv.x; acc[3][1] += av.w * bv.y;
            acc[3][2] += av.w * bv.z; acc[3][3] += av.w * bv.w;
        }
        __syncthreads();
    }

    float4 bb = *(const float4*)(bias + bn + tn);
#pragma unroll
    for (int u = 0; u < 4; ++u) {
        float4 r;
        r.x = acc[u][0] + bb.x; r.y = acc[u][1] + bb.y;
        r.z = acc[u][2] + bb.z; r.w = acc[u][3] + bb.w;
        if (act) {
            r.x = r.x > 0.f ? r.x : 0.01f * r.x;
            r.y = r.y > 0.f ? r.y : 0.01f * r.y;
            r.z = r.z > 0.f ? r.z : 0.01f * r.z;
            r.w = r.w > 0.f ? r.w : 0.01f * r.w;
        }
        *(float4*)(C + (size_t)(bm + tm + u) * Dm + bn + tn) = r;
    }
}

// ---------------- sparse masked attention: one warp per (row, head) ----------------
// Keys for row i: j=0, then j in [seg[i], i-1] (all same batch, strictly causal).
__global__ __launch_bounds__(256) void attn_kernel(
    const float* __restrict__ Q, const float* __restrict__ K,
    const float* __restrict__ V, const int* __restrict__ seg,
    float* __restrict__ O) {
    int i = blockIdx.x;
    int w = threadIdx.x >> 5;       // head
    int lane = threadIdx.x & 31;
    int col = w * DHd + lane * 2;

    float2 q = *(const float2*)(Q + (size_t)i * Dm + col);
    float m = -1e30f, l = 0.f;
    float2 acc = make_float2(0.f, 0.f);
    int s = seg[i];

    int j = 0;
    for (;;) {
        float2 k2 = *(const float2*)(K + (size_t)j * Dm + col);
        float p = q.x * k2.x + q.y * k2.y;
#pragma unroll
        for (int off = 16; off; off >>= 1)
            p += __shfl_xor_sync(0xffffffffu, p, off);
        p *= 0.125f;   // 1/sqrt(64)
        float nm = fmaxf(m, p);
        float sc = __expf(m - nm);
        float wg = __expf(p - nm);
        float2 v2 = *(const float2*)(V + (size_t)j * Dm + col);
        l = l * sc + wg;
        acc.x = acc.x * sc + wg * v2.x;
        acc.y = acc.y * sc + wg * v2.y;
        m = nm;
        if (j == 0) { j = s; if (j >= i || j <= 0) break; }
        else        { ++j;  if (j >= i) break; }
    }
    float inv = 1.f / l;
    float2 o = make_float2(acc.x * inv, acc.y * inv);
    *(float2*)(O + (size_t)i * Dm + col) = o;
}

// ---------------- layernorm (optional residual add): out = LN(X [+ Y]) * g + b ----------------
__global__ __launch_bounds__(128) void ln_kernel(
    const float* __restrict__ X, const float* __restrict__ Y,
    const float* __restrict__ g, const float* __restrict__ b,
    float* __restrict__ out) {
    int row = blockIdx.x;
    int tid = threadIdx.x;      // 128 threads, 4 elems each
    __shared__ float red[4];
    float v[4];
    float s = 0.f;
#pragma unroll
    for (int u = 0; u < 4; ++u) {
        int c = tid + u * 128;
        float t = X[(size_t)row * Dm + c];
        if (Y) t += Y[(size_t)row * Dm + c];
        v[u] = t; s += t;
    }
#pragma unroll
    for (int off = 16; off; off >>= 1) s += __shfl_xor_sync(0xffffffffu, s, off);
    if ((tid & 31) == 0) red[tid >> 5] = s;
    __syncthreads();
    float mean = (red[0] + red[1] + red[2] + red[3]) * (1.f / 512.f);
    float s2 = 0.f;
#pragma unroll
    for (int u = 0; u < 4; ++u) { float d = v[u] - mean; s2 += d * d; }
#pragma unroll
    for (int off = 16; off; off >>= 1) s2 += __shfl_xor_sync(0xffffffffu, s2, off);
    __syncthreads();
    if ((tid & 31) == 0) red[tid >> 5] = s2;
    __syncthreads();
    float var = (red[0] + red[1] + red[2] + red[3]) * (1.f / 512.f);
    float inv = rsqrtf(var + 1e-5f);
#pragma unroll
    for (int u = 0; u < 4; ++u) {
        int c = tid + u * 128;
        out[(size_t)row * Dm + c] = (v[u] - mean) * inv * g[c] + b[c];
    }
}

// ---------------- orchestration ----------------
extern "C" void kernel_launch(void* const* d_in, const int* in_sizes, int n_in,
                              void* d_out, int out_size) {
    const int*   idx = (const int*)d_in[0];
    const int*   seq = (const int*)d_in[1];
    const float* Wt  = (const float*)d_in[2];
    const float* bt  = (const float*)d_in[3];
    const float* Wa  = (const float*)d_in[4];
    const float* ba  = (const float*)d_in[5];
    const float* Wm  = (const float*)d_in[6];
    const float* bm  = (const float*)d_in[7];
    const float* sos = (const float*)d_in[8];
    const float* Wq  = (const float*)d_in[9];
    const float* bq  = (const float*)d_in[10];
    const float* Wk  = (const float*)d_in[11];
    const float* bk  = (const float*)d_in[12];
    const float* Wv  = (const float*)d_in[13];
    const float* bv  = (const float*)d_in[14];
    const float* Wo  = (const float*)d_in[15];
    const float* bo  = (const float*)d_in[16];
    const float* W1  = (const float*)d_in[17];
    const float* b1  = (const float*)d_in[18];
    const float* W2  = (const float*)d_in[19];
    const float* b2  = (const float*)d_in[20];
    const float* g1  = (const float*)d_in[21];
    const float* be1 = (const float*)d_in[22];
    const float* g2  = (const float*)d_in[23];
    const float* be2 = (const float*)d_in[24];
    float* out = (float*)d_out;

    float *x, *q, *k, *v, *o, *a, *xa, *h, *y; int* seg;
    cudaGetSymbolAddress((void**)&x,  g_x);
    cudaGetSymbolAddress((void**)&q,  g_q);
    cudaGetSymbolAddress((void**)&k,  g_k);
    cudaGetSymbolAddress((void**)&v,  g_v);
    cudaGetSymbolAddress((void**)&o,  g_o);
    cudaGetSymbolAddress((void**)&a,  g_a);
    cudaGetSymbolAddress((void**)&xa, g_xa);
    cudaGetSymbolAddress((void**)&h,  g_h);
    cudaGetSymbolAddress((void**)&y,  g_y);
    cudaGetSymbolAddress((void**)&seg, g_seg);

    embed_kernel<<<(L * Dm + 255) / 256, 256>>>(idx, Wt, bt, Wa, ba, Wm, bm, sos, x);
    scan_kernel<<<1, 1024>>>(seq, seg);

    dim3 gg(Dm / BN, L / BM);   // (8, 48)
    const float* in = x;
    for (int layer = 0; layer < 2; ++layer) {
        gemm_kernel<<<gg, 256>>>(in, Wq, bq, q, 0);
        gemm_kernel<<<gg, 256>>>(in, Wk, bk, k, 0);
        gemm_kernel<<<gg, 256>>>(in, Wv, bv, v, 0);
        attn_kernel<<<L, 256>>>(q, k, v, seg, o);
        gemm_kernel<<<gg, 256>>>(o, Wo, bo, a, 0);
        ln_kernel<<<L, 128>>>(a, nullptr, g1, be1, xa);
        gemm_kernel<<<gg, 256>>>(xa, W1, b1, h, 1);
        gemm_kernel<<<gg, 256>>>(h, W2, b2, y, 0);
        float* dst = (layer == 0) ? x : out;
        ln_kernel<<<L, 128>>>(xa, y, g2, be2, dst);
        in = x;
    }
}

// round 2
// speedup vs baseline: 1.5338x; 1.5338x over previous
#include <cuda_runtime.h>
#include <cuda_bf16.h>
#include <cstdint>

// ---------------- problem constants ----------------
#define L     3072
#define NTOK  3071
#define Dm    512
#define Hh    8
#define DHd   64
#define T_TYPES 15
#define N_ARGS  73
#define N_MAPS  3

typedef __nv_bfloat16 bf16;

// ---------------- scratch (static device globals; no allocations) ----------------
__device__ float g_q [L * Dm];
__device__ float g_k [L * Dm];
__device__ float g_v [L * Dm];
__device__ float g_a [L * Dm];
__device__ float g_xa[L * Dm];
__device__ float g_y [L * Dm];
__device__ int   g_seg[L];

// bf16 hi/lo planes for GEMM operands
__device__ bf16 g_xh [L * Dm];  __device__ bf16 g_xl [L * Dm];   // layer input x
__device__ bf16 g_oh [L * Dm];  __device__ bf16 g_ol [L * Dm];   // attn out
__device__ bf16 g_xah[L * Dm];  __device__ bf16 g_xal[L * Dm];   // ln1 out
__device__ bf16 g_hh [L * Dm];  __device__ bf16 g_hl [L * Dm];   // ffn hidden
// 6 weight matrices (Wq,Wk,Wv,Wo,W1,W2), each 512x512, hi+lo planes
__device__ bf16 g_Wh[6 * Dm * Dm];
__device__ bf16 g_Wl[6 * Dm * Dm];

// ---------------- small helpers ----------------
__device__ __forceinline__ void split_bf16(float x, bf16& h, bf16& l) {
    h = __float2bfloat16(x);
    l = __float2bfloat16(x - __bfloat162float(h));
}

__device__ __forceinline__ void cp16(uint32_t dst, const void* src) {
    asm volatile("cp.async.cg.shared.global [%0], [%1], 16;\n" :: "r"(dst), "l"(src));
}
__device__ __forceinline__ void ldsm4(uint32_t* r, uint32_t addr) {
    asm volatile("ldmatrix.sync.aligned.m8n8.x4.shared.b16 {%0,%1,%2,%3}, [%4];\n"
                 : "=r"(r[0]), "=r"(r[1]), "=r"(r[2]), "=r"(r[3]) : "r"(addr));
}
__device__ __forceinline__ void mma_bf16(float* d, const uint32_t* a, uint32_t b0, uint32_t b1) {
    asm volatile(
        "mma.sync.aligned.m16n8k16.row.col.f32.bf16.bf16.f32 "
        "{%0,%1,%2,%3}, {%4,%5,%6,%7}, {%8,%9}, {%0,%1,%2,%3};\n"
        : "+f"(d[0]), "+f"(d[1]), "+f"(d[2]), "+f"(d[3])
        : "r"(a[0]), "r"(a[1]), "r"(a[2]), "r"(a[3]), "r"(b0), "r"(b1));
}

// ---------------- weight conversion: fp32 -> bf16 hi/lo planes ----------------
__global__ void conv_kernel(const float* __restrict__ in, bf16* __restrict__ hi,
                            bf16* __restrict__ lo, int n4) {
    int i = blockIdx.x * blockDim.x + threadIdx.x;
    if (i >= n4) return;
    float4 x = ((const float4*)in)[i];
    bf16 h0, l0, h1, l1, h2, l2, h3, l3;
    split_bf16(x.x, h0, l0); split_bf16(x.y, h1, l1);
    split_bf16(x.z, h2, l2); split_bf16(x.w, h3, l3);
    __nv_bfloat162 ph0; ph0.x = h0; ph0.y = h1;
    __nv_bfloat162 ph1; ph1.x = h2; ph1.y = h3;
    __nv_bfloat162 pl0; pl0.x = l0; pl0.y = l1;
    __nv_bfloat162 pl1; pl1.x = l2; pl1.y = l3;
    ((__nv_bfloat162*)hi)[i * 2 + 0] = ph0;
    ((__nv_bfloat162*)hi)[i * 2 + 1] = ph1;
    ((__nv_bfloat162*)lo)[i * 2 + 0] = pl0;
    ((__nv_bfloat162*)lo)[i * 2 + 1] = pl1;
}

// ---------------- embedding: writes bf16 hi/lo planes directly ----------------
__global__ void embed_kernel(const int* __restrict__ idx,
                             const float* __restrict__ Wt, const float* __restrict__ bt,
                             const float* __restrict__ Wa, const float* __restrict__ ba,
                             const float* __restrict__ Wm, const float* __restrict__ bm,
                             const float* __restrict__ sos,
                             bf16* __restrict__ Xh, bf16* __restrict__ Xl) {
    int g = blockIdx.x * blockDim.x + threadIdx.x;
    if (g >= L * Dm) return;
    int n = g >> 9;
    int d = g & 511;
    float val;
    if (n == 0) {
        val = sos[d];
    } else {
        int id = idx[n - 1];
        int t = id / (N_ARGS * N_MAPS);
        int a = (id / N_MAPS) % N_ARGS;
        int m = id % N_MAPS;
        val = Wt[d * T_TYPES + t] + bt[d]
            + Wa[d * N_ARGS + a] + ba[d]
            + Wm[d * N_MAPS + m] + bm[d];
    }
    bf16 h, l; split_bf16(val, h, l);
    Xh[g] = h; Xl[g] = l;
}

// ---------------- scan: per-row attention segment start ----------------
__global__ void scan_kernel(const int* __restrict__ seq, int* __restrict__ segOut) {
    __shared__ int sA[L];
    __shared__ int sB[L];
    int tid = threadIdx.x;
    for (int i = tid; i < L; i += 1024)
        sA[i] = (i < NTOK && seq[i] == 0) ? 1 : 0;
    __syncthreads();
    int* src = sA; int* dst = sB;
    for (int d = 1; d < L; d <<= 1) {
        for (int i = tid; i < L; i += 1024)
            dst[i] = src[i] + (i >= d ? src[i - d] : 0);
        __syncthreads();
        int* t = src; src = dst; dst = t;
    }
    for (int i = tid; i < L; i += 1024)
        dst[i] = (i == 0) ? -1 : src[i - 1];
    __syncthreads();
    for (int i = tid; i < L; i += 1024) {
        int val = 0;
        if (i >= 1 && (i == 1 || dst[i] != dst[i - 1])) val = i;
        src[i] = val;
    }
    __syncthreads();
    for (int d = 1; d < L; d <<= 1) {
        for (int i = tid; i < L; i += 1024)
            dst[i] = max(src[i], (i >= d ? src[i - d] : 0));
        __syncthreads();
        int* t = src; src = dst; dst = t;
    }
    for (int i = tid; i < L; i += 1024)
        segOut[i] = src[i];
}

// ---------------- tensor-core GEMM: C[M,N] = (Ah+Al)[M,K] @ (Wh+Wl)[N,K]^T + bias ----------------
// 3-term split: C ~= Ah*Wh + Ah*Wl + Al*Wh, fp32 accumulate.
// Block tile 128x64, 8 warps (4m x 2n), BK=32, 2-stage cp.async pipeline.
// smem row stride: 40 bf16 = 80 bytes (16B-aligned, conflict-free ldmatrix).
#define SA_PLANE 10240   // 128*40*2 bytes
#define SB_PLANE 5120    // 64*40*2 bytes
#define SB_BASE  40960   // 4*SA_PLANE
#define SMEM_TOT 61440

__global__ __launch_bounds__(256) void gemm_bf16_kernel(
    const bf16* __restrict__ Ah, const bf16* __restrict__ Al,
    const bf16* __restrict__ Wh, const bf16* __restrict__ Wl,
    const float* __restrict__ bias,
    float* __restrict__ outF,
    bf16* __restrict__ outHi, bf16* __restrict__ outLo,
    int act)
{
    extern __shared__ __align__(16) unsigned char smem_raw[];
    const uint32_t sbase = (uint32_t)__cvta_generic_to_shared(smem_raw);
    const int tid = threadIdx.x;
    const int lane = tid & 31, wid = tid >> 5;
    const int bm = blockIdx.y * 128, bn = blockIdx.x * 64;
    const int warp_m = wid >> 1, warp_n = wid & 1;

    // load mapping: 16B chunks, row stride 80B in smem
    const int lr  = tid >> 2;          // A rows lr, lr+64; B row lr (0..63)
    const int lcB = (tid & 3) * 16;    // byte offset within smem row
    const int lcG = (tid & 3) * 8;     // bf16 col within gmem row

    // per-lane ldmatrix byte offsets
    const int a_off = (warp_m * 32 + (lane & 7) + ((lane >> 3) & 1) * 8) * 80
                    + ((lane >> 4) & 1) * 16;
    const int b_off = (warp_n * 32 + (lane & 7) + ((lane >> 4) & 1) * 8) * 80
                    + ((lane >> 3) & 1) * 16;

    const bf16* gAh0 = Ah + (size_t)(bm + lr) * Dm + lcG;
    const bf16* gAl0 = Al + (size_t)(bm + lr) * Dm + lcG;
    const bf16* gWh0 = Wh + (size_t)(bn + lr) * Dm + lcG;
    const bf16* gWl0 = Wl + (size_t)(bn + lr) * Dm + lcG;

    float acc[2][4][4];
#pragma unroll
    for (int mt = 0; mt < 2; ++mt)
#pragma unroll
        for (int nt = 0; nt < 4; ++nt)
#pragma unroll
            for (int u = 0; u < 4; ++u) acc[mt][nt][u] = 0.f;

#define LOADSTAGE(s, k0) do {                                              \
        uint32_t dA = sbase + (s) * 20480 + lr * 80 + lcB;                 \
        cp16(dA,                    gAh0 + (k0));                          \
        cp16(dA + SA_PLANE,         gAl0 + (k0));                          \
        cp16(dA + 64 * 80,          gAh0 + 64 * Dm + (k0));                \
        cp16(dA + 64 * 80 + SA_PLANE, gAl0 + 64 * Dm + (k0));              \
        uint32_t dB = sbase + SB_BASE + (s) * 10240 + lr * 80 + lcB;       \
        cp16(dB,            gWh0 + (k0));                                  \
        cp16(dB + SB_PLANE, gWl0 + (k0));                                  \
        asm volatile("cp.async.commit_group;\n" ::);                       \
    } while (0)

    LOADSTAGE(0, 0);

    for (int kt = 0; kt < 16; ++kt) {
        if (kt < 15) {
            LOADSTAGE((kt + 1) & 1, (kt + 1) * 32);
            asm volatile("cp.async.wait_group 1;\n" ::);
        } else {
            asm volatile("cp.async.wait_group 0;\n" ::);
        }
        __syncthreads();

        const int s = kt & 1;
        const uint32_t sA0 = sbase + s * 20480 + a_off;
        const uint32_t sB0 = sbase + SB_BASE + s * 10240 + b_off;
#pragma unroll
        for (int ks = 0; ks < 2; ++ks) {
            uint32_t ah[2][4], al[2][4], bh[2][4], bl[2][4];
#pragma unroll
            for (int mt = 0; mt < 2; ++mt) {
                uint32_t ad = sA0 + mt * 16 * 80 + ks * 32;
                ldsm4(ah[mt], ad);
                ldsm4(al[mt], ad + SA_PLANE);
            }
#pragma unroll
            for (int ng = 0; ng < 2; ++ng) {
                uint32_t bd = sB0 + ng * 16 * 80 + ks * 32;
                ldsm4(bh[ng], bd);
                ldsm4(bl[ng], bd + SB_PLANE);
            }
#pragma unroll
            for (int mt = 0; mt < 2; ++mt)
#pragma unroll
                for (int nt = 0; nt < 4; ++nt) {
                    const int ng = nt >> 1, hb = (nt & 1) * 2;
                    mma_bf16(acc[mt][nt], ah[mt], bh[ng][hb], bh[ng][hb + 1]);
                    mma_bf16(acc[mt][nt], ah[mt], bl[ng][hb], bl[ng][hb + 1]);
                    mma_bf16(acc[mt][nt], al[mt], bh[ng][hb], bh[ng][hb + 1]);
                }
        }
        __syncthreads();
    }
#undef LOADSTAGE

    // epilogue
    const int gid = lane >> 2, tig = lane & 3;
#pragma unroll
    for (int mt = 0; mt < 2; ++mt)
#pragma unroll
        for (int nt = 0; nt < 4; ++nt) {
            int row = bm + warp_m * 32 + mt * 16 + gid;
            int col = bn + warp_n * 32 + nt * 8 + tig * 2;
            float b0 = bias[col], b1 = bias[col + 1];
            float r0 = acc[mt][nt][0] + b0;
            float r1 = acc[mt][nt][1] + b1;
            float r2 = acc[mt][nt][2] + b0;
            float r3 = acc[mt][nt][3] + b1;
            if (act) {
                r0 = r0 > 0.f ? r0 : 0.01f * r0;
                r1 = r1 > 0.f ? r1 : 0.01f * r1;
                r2 = r2 > 0.f ? r2 : 0.01f * r2;
                r3 = r3 > 0.f ? r3 : 0.01f * r3;
            }
            if (outF) {
                *(float2*)(outF + (size_t)row * Dm + col)       = make_float2(r0, r1);
                *(float2*)(outF + (size_t)(row + 8) * Dm + col) = make_float2(r2, r3);
            }
            if (outHi) {
                bf16 h0, l0, h1, l1, h2, l2, h3, l3;
                split_bf16(r0, h0, l0); split_bf16(r1, h1, l1);
                split_bf16(r2, h2, l2); split_bf16(r3, h3, l3);
                __nv_bfloat162 t;
                t.x = h0; t.y = h1;
                *(__nv_bfloat162*)(outHi + (size_t)row * Dm + col) = t;
                t.x = l0; t.y = l1;
                *(__nv_bfloat162*)(outLo + (size_t)row * Dm + col) = t;
                t.x = h2; t.y = h3;
                *(__nv_bfloat162*)(outHi + (size_t)(row + 8) * Dm + col) = t;
                t.x = l2; t.y = l3;
                *(__nv_bfloat162*)(outLo + (size_t)(row + 8) * Dm + col) = t;
            }
        }
}

// ---------------- sparse masked attention: one warp per (row, head) ----------------
// Writes bf16 hi/lo planes (consumed only by Wo GEMM).
__global__ __launch_bounds__(256) void attn_kernel(
    const float* __restrict__ Q, const float* __restrict__ K,
    const float* __restrict__ V, const int* __restrict__ seg,
    bf16* __restrict__ Oh, bf16* __restrict__ Ol) {
    int i = blockIdx.x;
    int w = threadIdx.x >> 5;
    int lane = threadIdx.x & 31;
    int col = w * DHd + lane * 2;

    float2 q = *(const float2*)(Q + (size_t)i * Dm + col);
    float m = -1e30f, l = 0.f;
    float2 acc = make_float2(0.f, 0.f);
    int s = seg[i];

    int j = 0;
    for (;;) {
        float2 k2 = *(const float2*)(K + (size_t)j * Dm + col);
        float p = q.x * k2.x + q.y * k2.y;
#pragma unroll
        for (int off = 16; off; off >>= 1)
            p += __shfl_xor_sync(0xffffffffu, p, off);
        p *= 0.125f;
        float nm = fmaxf(m, p);
        float sc = __expf(m - nm);
        float wg = __expf(p - nm);
        float2 v2 = *(const float2*)(V + (size_t)j * Dm + col);
        l = l * sc + wg;
        acc.x = acc.x * sc + wg * v2.x;
        acc.y = acc.y * sc + wg * v2.y;
        m = nm;
        if (j == 0) { j = s; if (j >= i || j <= 0) break; }
        else        { ++j;  if (j >= i) break; }
    }
    float inv = 1.f / l;
    float ox = acc.x * inv, oy = acc.y * inv;
    bf16 hx, lx, hy, ly;
    split_bf16(ox, hx, lx); split_bf16(oy, hy, ly);
    __nv_bfloat162 t;
    t.x = hx; t.y = hy;
    *(__nv_bfloat162*)(Oh + (size_t)i * Dm + col) = t;
    t.x = lx; t.y = ly;
    *(__nv_bfloat162*)(Ol + (size_t)i * Dm + col) = t;
}

// ---------------- layernorm (optional residual) with fp32/bf16-plane outputs ----------------
__global__ __launch_bounds__(128) void ln_kernel(
    const float* __restrict__ X, const float* __restrict__ Y,
    const float* __restrict__ g, const float* __restrict__ b,
    float* __restrict__ outF, bf16* __restrict__ outHi, bf16* __restrict__ outLo) {
    int row = blockIdx.x;
    int tid = threadIdx.x;
    __shared__ float red[4];
    float v[4];
    float s = 0.f;
#pragma unroll
    for (int u = 0; u < 4; ++u) {
        int c = tid + u * 128;
        float t = X[(size_t)row * Dm + c];
        if (Y) t += Y[(size_t)row * Dm + c];
        v[u] = t; s += t;
    }
#pragma unroll
    for (int off = 16; off; off >>= 1) s += __shfl_xor_sync(0xffffffffu, s, off);
    if ((tid & 31) == 0) red[tid >> 5] = s;
    __syncthreads();
    float mean = (red[0] + red[1] + red[2] + red[3]) * (1.f / 512.f);
    float s2 = 0.f;
#pragma unroll
    for (int u = 0; u < 4; ++u) { float d = v[u] - mean; s2 += d * d; }
#pragma unroll
    for (int off = 16; off; off >>= 1) s2 += __shfl_xor_sync(0xffffffffu, s2, off);
    __syncthreads();
    if ((tid & 31) == 0) red[tid >> 5] = s2;
    __syncthreads();
    float var = (red[0] + red[1] + red[2] + red[3]) * (1.f / 512.f);
    float inv = rsqrtf(var + 1e-5f);
#pragma unroll
    for (int u = 0; u < 4; ++u) {
        int c = tid + u * 128;
        float r = (v[u] - mean) * inv * g[c] + b[c];
        if (outF) outF[(size_t)row * Dm + c] = r;
        if (outHi) {
            bf16 h, lo2; split_bf16(r, h, lo2);
            outHi[(size_t)row * Dm + c] = h;
            outLo[(size_t)row * Dm + c] = lo2;
        }
    }
}

// ---------------- orchestration ----------------
extern "C" void kernel_launch(void* const* d_in, const int* in_sizes, int n_in,
                              void* d_out, int out_size) {
    const int*   idx = (const int*)d_in[0];
    const int*   seq = (const int*)d_in[1];
    const float* Wt  = (const float*)d_in[2];
    const float* bt  = (const float*)d_in[3];
    const float* Wa  = (const float*)d_in[4];
    const float* ba  = (const float*)d_in[5];
    const float* Wm  = (const float*)d_in[6];
    const float* bm  = (const float*)d_in[7];
    const float* sos = (const float*)d_in[8];
    const float* Wq  = (const float*)d_in[9];
    const float* bq  = (const float*)d_in[10];
    const float* Wk  = (const float*)d_in[11];
    const float* bk  = (const float*)d_in[12];
    const float* Wv  = (const float*)d_in[13];
    const float* bv  = (const float*)d_in[14];
    const float* Wo  = (const float*)d_in[15];
    const float* bo  = (const float*)d_in[16];
    const float* W1  = (const float*)d_in[17];
    const float* b1  = (const float*)d_in[18];
    const float* W2  = (const float*)d_in[19];
    const float* b2  = (const float*)d_in[20];
    const float* g1  = (const float*)d_in[21];
    const float* be1 = (const float*)d_in[22];
    const float* g2  = (const float*)d_in[23];
    const float* be2 = (const float*)d_in[24];
    float* out = (float*)d_out;

    float *q, *k, *v, *a, *xa, *y; int* seg;
    bf16 *xh, *xl, *oh, *ol, *xah, *xal, *hh, *hl, *Wbh, *Wbl;
    cudaGetSymbolAddress((void**)&q,   g_q);
    cudaGetSymbolAddress((void**)&k,   g_k);
    cudaGetSymbolAddress((void**)&v,   g_v);
    cudaGetSymbolAddress((void**)&a,   g_a);
    cudaGetSymbolAddress((void**)&xa,  g_xa);
    cudaGetSymbolAddress((void**)&y,   g_y);
    cudaGetSymbolAddress((void**)&seg, g_seg);
    cudaGetSymbolAddress((void**)&xh,  g_xh);
    cudaGetSymbolAddress((void**)&xl,  g_xl);
    cudaGetSymbolAddress((void**)&oh,  g_oh);
    cudaGetSymbolAddress((void**)&ol,  g_ol);
    cudaGetSymbolAddress((void**)&xah, g_xah);
    cudaGetSymbolAddress((void**)&xal, g_xal);
    cudaGetSymbolAddress((void**)&hh,  g_hh);
    cudaGetSymbolAddress((void**)&hl,  g_hl);
    cudaGetSymbolAddress((void**)&Wbh, g_Wh);
    cudaGetSymbolAddress((void**)&Wbl, g_Wl);

    cudaFuncSetAttribute(gemm_bf16_kernel,
                         cudaFuncAttributeMaxDynamicSharedMemorySize, SMEM_TOT);

    const int WSZ = Dm * Dm;          // 262144
    const int n4  = WSZ / 4;          // 65536
    const float* Ws[6] = {Wq, Wk, Wv, Wo, W1, W2};
    for (int i = 0; i < 6; ++i)
        conv_kernel<<<n4 / 256, 256>>>(Ws[i], Wbh + (size_t)i * WSZ, Wbl + (size_t)i * WSZ, n4);

    embed_kernel<<<(L * Dm + 255) / 256, 256>>>(idx, Wt, bt, Wa, ba, Wm, bm, sos, xh, xl);
    scan_kernel<<<1, 1024>>>(seq, seg);

    dim3 gg(Dm / 64, L / 128);   // (8, 24)
    for (int layer = 0; layer < 2; ++layer) {
        bf16* Wqh = Wbh + 0 * (size_t)WSZ; bf16* Wql = Wbl + 0 * (size_t)WSZ;
        bf16* Wkh = Wbh + 1 * (size_t)WSZ; bf16* Wkl = Wbl + 1 * (size_t)WSZ;
        bf16* Wvh = Wbh + 2 * (size_t)WSZ; bf16* Wvl = Wbl + 2 * (size_t)WSZ;
        bf16* Woh = Wbh + 3 * (size_t)WSZ; bf16* Wol = Wbl + 3 * (size_t)WSZ;
        bf16* W1h = Wbh + 4 * (size_t)WSZ; bf16* W1l = Wbl + 4 * (size_t)WSZ;
        bf16* W2h = Wbh + 5 * (size_t)WSZ; bf16* W2l = Wbl + 5 * (size_t)WSZ;

        gemm_bf16_kernel<<<gg, 256, SMEM_TOT>>>(xh, xl, Wqh, Wql, bq, q, nullptr, nullptr, 0);
        gemm_bf16_kernel<<<gg, 256, SMEM_TOT>>>(xh, xl, Wkh, Wkl, bk, k, nullptr, nullptr, 0);
        gemm_bf16_kernel<<<gg, 256, SMEM_TOT>>>(xh, xl, Wvh, Wvl, bv, v, nullptr, nullptr, 0);
        attn_kernel<<<L, 256>>>(q, k, v, seg, oh, ol);
        gemm_bf16_kernel<<<gg, 256, SMEM_TOT>>>(oh, ol, Woh, Wol, bo, a, nullptr, nullptr, 0);
        ln_kernel<<<L, 128>>>(a, nullptr, g1, be1, xa, xah, xal);
        gemm_bf16_kernel<<<gg, 256, SMEM_TOT>>>(xah, xal, W1h, W1l, b1, nullptr, hh, hl, 1);
        gemm_bf16_kernel<<<gg, 256, SMEM_TOT>>>(hh, hl, W2h, W2l, b2, y, nullptr, nullptr, 0);
        if (layer == 0)
            ln_kernel<<<L, 128>>>(xa, y, g2, be2, nullptr, xh, xl);
        else
            ln_kernel<<<L, 128>>>(xa, y, g2, be2, out, nullptr, nullptr);
    }
}

// round 3
// speedup vs baseline: 1.6049x; 1.0463x over previous
#include <cuda_runtime.h>
#include <cuda_bf16.h>
#include <cstdint>

// ---------------- problem constants ----------------
#define L     3072
#define NTOK  3071
#define Dm    512
#define Hh    8
#define DHd   64
#define T_TYPES 15
#define N_ARGS  73
#define N_MAPS  3

typedef __nv_bfloat16 bf16;

// ---------------- scratch (static device globals; no allocations) ----------------
__device__ float g_qkv[L * 3 * Dm];
__device__ float g_a [L * Dm];
__device__ float g_xa[L * Dm];
__device__ float g_y [L * Dm];
__device__ float g_bqkv[3 * Dm];
__device__ int   g_seg[L];

// bf16 hi/lo planes for GEMM operands
__device__ bf16 g_xh [L * Dm];  __device__ bf16 g_xl [L * Dm];   // layer input x
__device__ bf16 g_oh [L * Dm];  __device__ bf16 g_ol [L * Dm];   // attn out
__device__ bf16 g_xah[L * Dm];  __device__ bf16 g_xal[L * Dm];   // ln1 out
__device__ bf16 g_hh [L * Dm];  __device__ bf16 g_hl [L * Dm];   // ffn hidden
// 6 weight matrices (Wq,Wk,Wv,Wo,W1,W2), each 512x512, hi+lo planes.
// Slots 0..2 (Wq,Wk,Wv) are contiguous => fused QKV weight [1536,512].
__device__ bf16 g_Wh[6 * Dm * Dm];
__device__ bf16 g_Wl[6 * Dm * Dm];

// ---------------- small helpers ----------------
__device__ __forceinline__ void split_bf16(float x, bf16& h, bf16& l) {
    h = __float2bfloat16(x);
    l = __float2bfloat16(x - __bfloat162float(h));
}
__device__ __forceinline__ void cp16(uint32_t dst, const void* src) {
    asm volatile("cp.async.cg.shared.global [%0], [%1], 16;\n" :: "r"(dst), "l"(src));
}
__device__ __forceinline__ void ldsm4(uint32_t* r, uint32_t addr) {
    asm volatile("ldmatrix.sync.aligned.m8n8.x4.shared.b16 {%0,%1,%2,%3}, [%4];\n"
                 : "=r"(r[0]), "=r"(r[1]), "=r"(r[2]), "=r"(r[3]) : "r"(addr));
}
__device__ __forceinline__ void mma_bf16(float* d, const uint32_t* a, uint32_t b0, uint32_t b1) {
    asm volatile(
        "mma.sync.aligned.m16n8k16.row.col.f32.bf16.bf16.f32 "
        "{%0,%1,%2,%3}, {%4,%5,%6,%7}, {%8,%9}, {%0,%1,%2,%3};\n"
        : "+f"(d[0]), "+f"(d[1]), "+f"(d[2]), "+f"(d[3])
        : "r"(a[0]), "r"(a[1]), "r"(a[2]), "r"(a[3]), "r"(b0), "r"(b1));
}

// ---------------- weight conversion: 3 matrices per launch ----------------
__global__ void conv3_kernel(const float* __restrict__ w0, const float* __restrict__ w1,
                             const float* __restrict__ w2,
                             bf16* __restrict__ hi, bf16* __restrict__ lo) {
    const int n4 = Dm * Dm / 4;
    int i = blockIdx.x * blockDim.x + threadIdx.x;
    if (i >= n4) return;
    int wsel = blockIdx.y;
    const float* in = (wsel == 0) ? w0 : (wsel == 1) ? w1 : w2;
    size_t base = (size_t)wsel * Dm * Dm;
    float4 x = ((const float4*)in)[i];
    bf16 h0, l0, h1, l1, h2, l2, h3, l3;
    split_bf16(x.x, h0, l0); split_bf16(x.y, h1, l1);
    split_bf16(x.z, h2, l2); split_bf16(x.w, h3, l3);
    __nv_bfloat162 t;
    __nv_bfloat162* H = (__nv_bfloat162*)(hi + base);
    __nv_bfloat162* Lo = (__nv_bfloat162*)(lo + base);
    t.x = h0; t.y = h1; H[i * 2 + 0] = t;
    t.x = h2; t.y = h3; H[i * 2 + 1] = t;
    t.x = l0; t.y = l1; Lo[i * 2 + 0] = t;
    t.x = l2; t.y = l3; Lo[i * 2 + 1] = t;
}

// ---------------- bias concat for fused QKV ----------------
__global__ void biascat_kernel(const float* __restrict__ bq, const float* __restrict__ bk,
                               const float* __restrict__ bv, float* __restrict__ out) {
    int i = threadIdx.x + blockIdx.x * blockDim.x;
    if (i >= 3 * Dm) return;
    const float* src = (i < Dm) ? bq : (i < 2 * Dm) ? bk : bv;
    out[i] = src[i & (Dm - 1)];
}

// ---------------- embedding: writes bf16 hi/lo planes directly ----------------
__global__ void embed_kernel(const int* __restrict__ idx,
                             const float* __restrict__ Wt, const float* __restrict__ bt,
                             const float* __restrict__ Wa, const float* __restrict__ ba,
                             const float* __restrict__ Wm, const float* __restrict__ bm,
                             const float* __restrict__ sos,
                             bf16* __restrict__ Xh, bf16* __restrict__ Xl) {
    int g = blockIdx.x * blockDim.x + threadIdx.x;
    if (g >= L * Dm) return;
    int n = g >> 9;
    int d = g & 511;
    float val;
    if (n == 0) {
        val = sos[d];
    } else {
        int id = idx[n - 1];
        int t = id / (N_ARGS * N_MAPS);
        int a = (id / N_MAPS) % N_ARGS;
        int m = id % N_MAPS;
        val = Wt[d * T_TYPES + t] + bt[d]
            + Wa[d * N_ARGS + a] + ba[d]
            + Wm[d * N_MAPS + m] + bm[d];
    }
    bf16 h, l; split_bf16(val, h, l);
    Xh[g] = h; Xl[g] = l;
}

// ---------------- scan: per-row attention segment start ----------------
__global__ void scan_kernel(const int* __restrict__ seq, int* __restrict__ segOut) {
    __shared__ int sA[L];
    __shared__ int sB[L];
    int tid = threadIdx.x;
    for (int i = tid; i < L; i += 1024)
        sA[i] = (i < NTOK && seq[i] == 0) ? 1 : 0;
    __syncthreads();
    int* src = sA; int* dst = sB;
    for (int d = 1; d < L; d <<= 1) {
        for (int i = tid; i < L; i += 1024)
            dst[i] = src[i] + (i >= d ? src[i - d] : 0);
        __syncthreads();
        int* t = src; src = dst; dst = t;
    }
    for (int i = tid; i < L; i += 1024)
        dst[i] = (i == 0) ? -1 : src[i - 1];
    __syncthreads();
    for (int i = tid; i < L; i += 1024) {
        int val = 0;
        if (i >= 1 && (i == 1 || dst[i] != dst[i - 1])) val = i;
        src[i] = val;
    }
    __syncthreads();
    for (int d = 1; d < L; d <<= 1) {
        for (int i = tid; i < L; i += 1024)
            dst[i] = max(src[i], (i >= d ? src[i - d] : 0));
        __syncthreads();
        int* t = src; src = dst; dst = t;
    }
    for (int i = tid; i < L; i += 1024)
        segOut[i] = src[i];
}

// ---------------- tensor-core GEMM: C[M,N] = (Ah+Al)[M,K=512] @ (Wh+Wl)[N,K=512]^T + bias ----------------
// 3-term split: C ~= Ah*Wh + Ah*Wl + Al*Wh, fp32 accumulate.
// Block tile 128x64, 8 warps (4m x 2n), BK=32, 2-stage cp.async pipeline.
// smem row stride: 40 bf16 = 80 bytes.
#define SA_PLANE 10240
#define SB_PLANE 5120
#define SB_BASE  40960
#define SMEM_TOT 61440

__global__ __launch_bounds__(256) void gemm_bf16_kernel(
    const bf16* __restrict__ Ah, const bf16* __restrict__ Al,
    const bf16* __restrict__ Wh, const bf16* __restrict__ Wl,
    const float* __restrict__ bias,
    float* __restrict__ outF,
    bf16* __restrict__ outHi, bf16* __restrict__ outLo,
    int act, int ldc)
{
    extern __shared__ __align__(16) unsigned char smem_raw[];
    const uint32_t sbase = (uint32_t)__cvta_generic_to_shared(smem_raw);
    const int tid = threadIdx.x;
    const int lane = tid & 31, wid = tid >> 5;
    const int bm = blockIdx.y * 128, bn = blockIdx.x * 64;
    const int warp_m = wid >> 1, warp_n = wid & 1;

    const int lr  = tid >> 2;
    const int lcB = (tid & 3) * 16;
    const int lcG = (tid & 3) * 8;

    const int a_off = (warp_m * 32 + (lane & 7) + ((lane >> 3) & 1) * 8) * 80
                    + ((lane >> 4) & 1) * 16;
    const int b_off = (warp_n * 32 + (lane & 7) + ((lane >> 4) & 1) * 8) * 80
                    + ((lane >> 3) & 1) * 16;

    const bf16* gAh0 = Ah + (size_t)(bm + lr) * Dm + lcG;
    const bf16* gAl0 = Al + (size_t)(bm + lr) * Dm + lcG;
    const bf16* gWh0 = Wh + (size_t)(bn + lr) * Dm + lcG;
    const bf16* gWl0 = Wl + (size_t)(bn + lr) * Dm + lcG;

    float acc[2][4][4];
#pragma unroll
    for (int mt = 0; mt < 2; ++mt)
#pragma unroll
        for (int nt = 0; nt < 4; ++nt)
#pragma unroll
            for (int u = 0; u < 4; ++u) acc[mt][nt][u] = 0.f;

#define LOADSTAGE(s, k0) do {                                              \
        uint32_t dA = sbase + (s) * 20480 + lr * 80 + lcB;                 \
        cp16(dA,                    gAh0 + (k0));                          \
        cp16(dA + SA_PLANE,         gAl0 + (k0));                          \
        cp16(dA + 64 * 80,          gAh0 + 64 * Dm + (k0));                \
        cp16(dA + 64 * 80 + SA_PLANE, gAl0 + 64 * Dm + (k0));              \
        uint32_t dB = sbase + SB_BASE + (s) * 10240 + lr * 80 + lcB;       \
        cp16(dB,            gWh0 + (k0));                                  \
        cp16(dB + SB_PLANE, gWl0 + (k0));                                  \
        asm volatile("cp.async.commit_group;\n" ::);                       \
    } while (0)

    LOADSTAGE(0, 0);

    for (int kt = 0; kt < 16; ++kt) {
        if (kt < 15) {
            LOADSTAGE((kt + 1) & 1, (kt + 1) * 32);
            asm volatile("cp.async.wait_group 1;\n" ::);
        } else {
            asm volatile("cp.async.wait_group 0;\n" ::);
        }
        __syncthreads();

        const int s = kt & 1;
        const uint32_t sA0 = sbase + s * 20480 + a_off;
        const uint32_t sB0 = sbase + SB_BASE + s * 10240 + b_off;
#pragma unroll
        for (int ks = 0; ks < 2; ++ks) {
            uint32_t ah[2][4], al[2][4], bh[2][4], bl[2][4];
#pragma unroll
            for (int mt = 0; mt < 2; ++mt) {
                uint32_t ad = sA0 + mt * 16 * 80 + ks * 32;
                ldsm4(ah[mt], ad);
                ldsm4(al[mt], ad + SA_PLANE);
            }
#pragma unroll
            for (int ng = 0; ng < 2; ++ng) {
                uint32_t bd = sB0 + ng * 16 * 80 + ks * 32;
                ldsm4(bh[ng], bd);
                ldsm4(bl[ng], bd + SB_PLANE);
            }
#pragma unroll
            for (int mt = 0; mt < 2; ++mt)
#pragma unroll
                for (int nt = 0; nt < 4; ++nt) {
                    const int ng = nt >> 1, hb = (nt & 1) * 2;
                    mma_bf16(acc[mt][nt], ah[mt], bh[ng][hb], bh[ng][hb + 1]);
                    mma_bf16(acc[mt][nt], ah[mt], bl[ng][hb], bl[ng][hb + 1]);
                    mma_bf16(acc[mt][nt], al[mt], bh[ng][hb], bh[ng][hb + 1]);
                }
        }
        __syncthreads();
    }
#undef LOADSTAGE

    const int gid = lane >> 2, tig = lane & 3;
#pragma unroll
    for (int mt = 0; mt < 2; ++mt)
#pragma unroll
        for (int nt = 0; nt < 4; ++nt) {
            int row = bm + warp_m * 32 + mt * 16 + gid;
            int col = bn + warp_n * 32 + nt * 8 + tig * 2;
            float b0 = bias[col], b1 = bias[col + 1];
            float r0 = acc[mt][nt][0] + b0;
            float r1 = acc[mt][nt][1] + b1;
            float r2 = acc[mt][nt][2] + b0;
            float r3 = acc[mt][nt][3] + b1;
            if (act) {
                r0 = r0 > 0.f ? r0 : 0.01f * r0;
                r1 = r1 > 0.f ? r1 : 0.01f * r1;
                r2 = r2 > 0.f ? r2 : 0.01f * r2;
                r3 = r3 > 0.f ? r3 : 0.01f * r3;
            }
            if (outF) {
                *(float2*)(outF + (size_t)row * ldc + col)       = make_float2(r0, r1);
                *(float2*)(outF + (size_t)(row + 8) * ldc + col) = make_float2(r2, r3);
            }
            if (outHi) {
                bf16 h0, l0, h1, l1, h2, l2, h3, l3;
                split_bf16(r0, h0, l0); split_bf16(r1, h1, l1);
                split_bf16(r2, h2, l2); split_bf16(r3, h3, l3);
                __nv_bfloat162 t;
                t.x = h0; t.y = h1;
                *(__nv_bfloat162*)(outHi + (size_t)row * ldc + col) = t;
                t.x = l0; t.y = l1;
                *(__nv_bfloat162*)(outLo + (size_t)row * ldc + col) = t;
                t.x = h2; t.y = h3;
                *(__nv_bfloat162*)(outHi + (size_t)(row + 8) * ldc + col) = t;
                t.x = l2; t.y = l3;
                *(__nv_bfloat162*)(outLo + (size_t)(row + 8) * ldc + col) = t;
            }
        }
}

// ---------------- sparse masked attention v2: keys parallel across lanes ----------------
// Block per row i; warp per head. Keys: ordinal t in [0,n): j = (t==0)?0 : s+t-1.
// Chunked online softmax: one max-reduce + one sum-reduce per 32 keys.
__global__ __launch_bounds__(256) void attn_kernel(
    const float* __restrict__ QKV, const int* __restrict__ seg,
    bf16* __restrict__ Oh, bf16* __restrict__ Ol) {
    int i = blockIdx.x;
    int h = threadIdx.x >> 5;
    int lane = threadIdx.x & 31;
    __shared__ float qs[Dm];

    for (int c = threadIdx.x; c < Dm; c += 256)
        qs[c] = QKV[(size_t)i * 1536 + c];
    __syncthreads();

    const float* Kbase = QKV + Dm;       // K plane at col offset 512
    const float* Vbase = QKV + 2 * Dm;   // V plane at col offset 1024
    const float4* qh4 = (const float4*)(qs + h * DHd);

    int s = seg[i];
    int n = 1 + max(0, i - s);

    float m = -1e30f, l = 0.f;
    float2 oacc = make_float2(0.f, 0.f);

    for (int base = 0; base < n; base += 32) {
        int t = base + lane;
        bool valid = t < n;
        int j = (t == 0) ? 0 : s + t - 1;
        float sc = -1e30f;
        if (valid) {
            const float4* kr = (const float4*)(Kbase + (size_t)j * 1536 + h * DHd);
            float a0 = 0.f, a1 = 0.f;
#pragma unroll
            for (int d4 = 0; d4 < 16; d4 += 2) {
                float4 k0 = kr[d4],     q0 = qh4[d4];
                float4 k1 = kr[d4 + 1], q1 = qh4[d4 + 1];
                a0 += q0.x * k0.x + q0.y * k0.y + q0.z * k0.z + q0.w * k0.w;
                a1 += q1.x * k1.x + q1.y * k1.y + q1.z * k1.z + q1.w * k1.w;
            }
            sc = (a0 + a1) * 0.125f;
        }
        float cm = sc;
#pragma unroll
        for (int off = 16; off; off >>= 1)
            cm = fmaxf(cm, __shfl_xor_sync(0xffffffffu, cm, off));
        float nm = fmaxf(m, cm);
        float scale = __expf(m - nm);
        float w = valid ? __expf(sc - nm) : 0.f;
        float ws = w;
#pragma unroll
        for (int off = 16; off; off >>= 1)
            ws += __shfl_xor_sync(0xffffffffu, ws, off);
        l = l * scale + ws;
        oacc.x *= scale; oacc.y *= scale;

        int cnt = min(32, n - base);
        const float* vcol = Vbase + h * DHd + lane * 2;
        for (int t2 = 0; t2 < cnt; ++t2) {
            float wj = __shfl_sync(0xffffffffu, w, t2);
            int jj   = __shfl_sync(0xffffffffu, j, t2);
            float2 v2 = *(const float2*)(vcol + (size_t)jj * 1536);
            oacc.x += wj * v2.x;
            oacc.y += wj * v2.y;
        }
        m = nm;
    }

    float inv = 1.f / l;
    float ox = oacc.x * inv, oy = oacc.y * inv;
    bf16 hx, lx, hy, ly;
    split_bf16(ox, hx, lx); split_bf16(oy, hy, ly);
    int col = h * DHd + lane * 2;
    __nv_bfloat162 t2o;
    t2o.x = hx; t2o.y = hy;
    *(__nv_bfloat162*)(Oh + (size_t)i * Dm + col) = t2o;
    t2o.x = lx; t2o.y = ly;
    *(__nv_bfloat162*)(Ol + (size_t)i * Dm + col) = t2o;
}

// ---------------- layernorm (optional residual) with fp32/bf16-plane outputs ----------------
__global__ __launch_bounds__(128) void ln_kernel(
    const float* __restrict__ X, const float* __restrict__ Y,
    const float* __restrict__ g, const float* __restrict__ b,
    float* __restrict__ outF, bf16* __restrict__ outHi, bf16* __restrict__ outLo) {
    int row = blockIdx.x;
    int tid = threadIdx.x;
    __shared__ float red[4];
    float v[4];
    float s = 0.f;
#pragma unroll
    for (int u = 0; u < 4; ++u) {
        int c = tid + u * 128;
        float t = X[(size_t)row * Dm + c];
        if (Y) t += Y[(size_t)row * Dm + c];
        v[u] = t; s += t;
    }
#pragma unroll
    for (int off = 16; off; off >>= 1) s += __shfl_xor_sync(0xffffffffu, s, off);
    if ((tid & 31) == 0) red[tid >> 5] = s;
    __syncthreads();
    float mean = (red[0] + red[1] + red[2] + red[3]) * (1.f / 512.f);
    float s2 = 0.f;
#pragma unroll
    for (int u = 0; u < 4; ++u) { float d = v[u] - mean; s2 += d * d; }
#pragma unroll
    for (int off = 16; off; off >>= 1) s2 += __shfl_xor_sync(0xffffffffu, s2, off);
    __syncthreads();
    if ((tid & 31) == 0) red[tid >> 5] = s2;
    __syncthreads();
    float var = (red[0] + red[1] + red[2] + red[3]) * (1.f / 512.f);
    float inv = rsqrtf(var + 1e-5f);
#pragma unroll
    for (int u = 0; u < 4; ++u) {
        int c = tid + u * 128;
        float r = (v[u] - mean) * inv * g[c] + b[c];
        if (outF) outF[(size_t)row * Dm + c] = r;
        if (outHi) {
            bf16 h, lo2; split_bf16(r, h, lo2);
            outHi[(size_t)row * Dm + c] = h;
            outLo[(size_t)row * Dm + c] = lo2;
        }
    }
}

// ---------------- orchestration ----------------
extern "C" void kernel_launch(void* const* d_in, const int* in_sizes, int n_in,
                              void* d_out, int out_size) {
    const int*   idx = (const int*)d_in[0];
    const int*   seq = (const int*)d_in[1];
    const float* Wt  = (const float*)d_in[2];
    const float* bt  = (const float*)d_in[3];
    const float* Wa  = (const float*)d_in[4];
    const float* ba  = (const float*)d_in[5];
    const float* Wm  = (const float*)d_in[6];
    const float* bm  = (const float*)d_in[7];
    const float* sos = (const float*)d_in[8];
    const float* Wq  = (const float*)d_in[9];
    const float* bq  = (const float*)d_in[10];
    const float* Wk  = (const float*)d_in[11];
    const float* bk  = (const float*)d_in[12];
    const float* Wv  = (const float*)d_in[13];
    const float* bv  = (const float*)d_in[14];
    const float* Wo  = (const float*)d_in[15];
    const float* bo  = (const float*)d_in[16];
    const float* W1  = (const float*)d_in[17];
    const float* b1  = (const float*)d_in[18];
    const float* W2  = (const float*)d_in[19];
    const float* b2  = (const float*)d_in[20];
    const float* g1  = (const float*)d_in[21];
    const float* be1 = (const float*)d_in[22];
    const float* g2  = (const float*)d_in[23];
    const float* be2 = (const float*)d_in[24];
    float* out = (float*)d_out;

    float *qkv, *a, *xa, *y, *bqkv; int* seg;
    bf16 *xh, *xl, *oh, *ol, *xah, *xal, *hh, *hl, *Wbh, *Wbl;
    cudaGetSymbolAddress((void**)&qkv, g_qkv);
    cudaGetSymbolAddress((void**)&a,   g_a);
    cudaGetSymbolAddress((void**)&xa,  g_xa);
    cudaGetSymbolAddress((void**)&y,   g_y);
    cudaGetSymbolAddress((void**)&bqkv, g_bqkv);
    cudaGetSymbolAddress((void**)&seg, g_seg);
    cudaGetSymbolAddress((void**)&xh,  g_xh);
    cudaGetSymbolAddress((void**)&xl,  g_xl);
    cudaGetSymbolAddress((void**)&oh,  g_oh);
    cudaGetSymbolAddress((void**)&ol,  g_ol);
    cudaGetSymbolAddress((void**)&xah, g_xah);
    cudaGetSymbolAddress((void**)&xal, g_xal);
    cudaGetSymbolAddress((void**)&hh,  g_hh);
    cudaGetSymbolAddress((void**)&hl,  g_hl);
    cudaGetSymbolAddress((void**)&Wbh, g_Wh);
    cudaGetSymbolAddress((void**)&Wbl, g_Wl);

    cudaFuncSetAttribute(gemm_bf16_kernel,
                         cudaFuncAttributeMaxDynamicSharedMemorySize, SMEM_TOT);

    const size_t WSZ = (size_t)Dm * Dm;
    const int n4 = (int)WSZ / 4;
    // launches 1,2: weight conversion (3 matrices each)
    dim3 cg(n4 / 256, 3);
    conv3_kernel<<<cg, 256>>>(Wq, Wk, Wv, Wbh, Wbl);
    conv3_kernel<<<cg, 256>>>(Wo, W1, W2, Wbh + 3 * WSZ, Wbl + 3 * WSZ);
    // launch 3: bias concat
    biascat_kernel<<<6, 256>>>(bq, bk, bv, bqkv);
    // launch 4: embedding
    embed_kernel<<<(L * Dm + 255) / 256, 256>>>(idx, Wt, bt, Wa, ba, Wm, bm, sos, xh, xl);
    // launch 5: scan
    scan_kernel<<<1, 1024>>>(seq, seg);

    dim3 ggQKV(3 * Dm / 64, L / 128);   // (24, 24) = 576 blocks
    dim3 gg(Dm / 64, L / 128);          // (8, 24)  = 192 blocks
    for (int layer = 0; layer < 2; ++layer) {
        bf16* Woh = Wbh + 3 * WSZ; bf16* Wol = Wbl + 3 * WSZ;
        bf16* W1h = Wbh + 4 * WSZ; bf16* W1l = Wbl + 4 * WSZ;
        bf16* W2h = Wbh + 5 * WSZ; bf16* W2l = Wbl + 5 * WSZ;

        // launch 6 (profiled): fused QKV GEMM, N=1536
        gemm_bf16_kernel<<<ggQKV, 256, SMEM_TOT>>>(xh, xl, Wbh, Wbl, bqkv,
                                                   qkv, nullptr, nullptr, 0, 1536);
        attn_kernel<<<L, 256>>>(qkv, seg, oh, ol);
        gemm_bf16_kernel<<<gg, 256, SMEM_TOT>>>(oh, ol, Woh, Wol, bo, a, nullptr, nullptr, 0, Dm);
        ln_kernel<<<L, 128>>>(a, nullptr, g1, be1, xa, xah, xal);
        gemm_bf16_kernel<<<gg, 256, SMEM_TOT>>>(xah, xal, W1h, W1l, b1,
                                                nullptr, hh, hl, 1, Dm);
        gemm_bf16_kernel<<<gg, 256, SMEM_TOT>>>(hh, hl, W2h, W2l, b2, y, nullptr, nullptr, 0, Dm);
        if (layer == 0)
            ln_kernel<<<L, 128>>>(xa, y, g2, be2, nullptr, xh, xl);
        else
            ln_kernel<<<L, 128>>>(xa, y, g2, be2, out, nullptr, nullptr);
    }
}

// round 6
// speedup vs baseline: 1.8287x; 1.1395x over previous
#include <cuda_runtime.h>
#include <cuda_fp16.h>
#include <cstdint>

// ---------------- problem constants ----------------
#define L     3072
#define NTOK  3071
#define Dm    512
#define Hh    8
#define DHd   64
#define T_TYPES 15
#define N_ARGS  73
#define N_MAPS  3

typedef __half f16;

// ---------------- scratch (static device globals; no allocations) ----------------
__device__ float g_qkv[L * 3 * Dm];
__device__ float g_a [L * Dm];
__device__ float g_xa[L * Dm];
__device__ float g_y [L * Dm];
__device__ float g_bqkv[3 * Dm];
__device__ int   g_seg[L];

// fp16 hi/lo planes for activations; weights hi-only
__device__ f16 g_xh [L * Dm];  __device__ f16 g_xl [L * Dm];
__device__ f16 g_oh [L * Dm];  __device__ f16 g_ol [L * Dm];
__device__ f16 g_xah[L * Dm];  __device__ f16 g_xal[L * Dm];
__device__ f16 g_hh [L * Dm];  __device__ f16 g_hl [L * Dm];
__device__ f16 g_Wh[6 * Dm * Dm];   // Wq,Wk,Wv | Wo | W1 | W2 (hi plane only)

// ---------------- helpers ----------------
__device__ __forceinline__ void split_f16(float x, f16& h, f16& l) {
    h = __float2half_rn(x);
    l = __float2half_rn(x - __half2float(h));
}
__device__ __forceinline__ void cp16(uint32_t dst, const void* src) {
    asm volatile("cp.async.cg.shared.global [%0], [%1], 16;\n" :: "r"(dst), "l"(src));
}
__device__ __forceinline__ void ldsm4(uint32_t* r, uint32_t addr) {
    asm volatile("ldmatrix.sync.aligned.m8n8.x4.shared.b16 {%0,%1,%2,%3}, [%4];\n"
                 : "=r"(r[0]), "=r"(r[1]), "=r"(r[2]), "=r"(r[3]) : "r"(addr));
}
__device__ __forceinline__ void mma_f16(float* d, const uint32_t* a, uint32_t b0, uint32_t b1) {
    asm volatile(
        "mma.sync.aligned.m16n8k16.row.col.f32.f16.f16.f32 "
        "{%0,%1,%2,%3}, {%4,%5,%6,%7}, {%8,%9}, {%0,%1,%2,%3};\n"
        : "+f"(d[0]), "+f"(d[1]), "+f"(d[2]), "+f"(d[3])
        : "r"(a[0]), "r"(a[1]), "r"(a[2]), "r"(a[3]), "r"(b0), "r"(b1));
}

// ---------------- weight conversion: all 6 matrices, hi plane only ----------------
__global__ void conv6_kernel(const float* __restrict__ w0, const float* __restrict__ w1,
                             const float* __restrict__ w2, const float* __restrict__ w3,
                             const float* __restrict__ w4, const float* __restrict__ w5,
                             f16* __restrict__ hi) {
    const int n4 = Dm * Dm / 4;
    int i = blockIdx.x * blockDim.x + threadIdx.x;
    if (i >= n4) return;
    int wsel = blockIdx.y;
    const float* in = (wsel == 0) ? w0 : (wsel == 1) ? w1 : (wsel == 2) ? w2
                    : (wsel == 3) ? w3 : (wsel == 4) ? w4 : w5;
    size_t base = (size_t)wsel * Dm * Dm;
    float4 x = ((const float4*)in)[i];
    __half2 p0, p1;
    p0.x = __float2half_rn(x.x); p0.y = __float2half_rn(x.y);
    p1.x = __float2half_rn(x.z); p1.y = __float2half_rn(x.w);
    __half2* H = (__half2*)(hi + base);
    H[i * 2 + 0] = p0;
    H[i * 2 + 1] = p1;
}

// ---------------- bias concat for fused QKV ----------------
__global__ void biascat_kernel(const float* __restrict__ bq, const float* __restrict__ bk,
                               const float* __restrict__ bv, float* __restrict__ out) {
    int i = threadIdx.x + blockIdx.x * blockDim.x;
    if (i >= 3 * Dm) return;
    const float* src = (i < Dm) ? bq : (i < 2 * Dm) ? bk : bv;
    out[i] = src[i & (Dm - 1)];
}

// ---------------- embedding: fp16 hi/lo planes ----------------
__global__ void embed_kernel(const int* __restrict__ idx,
                             const float* __restrict__ Wt, const float* __restrict__ bt,
                             const float* __restrict__ Wa, const float* __restrict__ ba,
                             const float* __restrict__ Wm, const float* __restrict__ bm,
                             const float* __restrict__ sos,
                             f16* __restrict__ Xh, f16* __restrict__ Xl) {
    int g = blockIdx.x * blockDim.x + threadIdx.x;
    if (g >= L * Dm) return;
    int n = g >> 9;
    int d = g & 511;
    float val;
    if (n == 0) {
        val = sos[d];
    } else {
        int id = idx[n - 1];
        int t = id / (N_ARGS * N_MAPS);
        int a = (id / N_MAPS) % N_ARGS;
        int m = id % N_MAPS;
        val = Wt[d * T_TYPES + t] + bt[d]
            + Wa[d * N_ARGS + a] + ba[d]
            + Wm[d * N_MAPS + m] + bm[d];
    }
    f16 h, l; split_f16(val, h, l);
    Xh[g] = h; Xl[g] = l;
}

// ---------------- scan: single warp/block max-scan ----------------
// seg[0]=0; for i>=1: seg[i] = max(1, M[i-1]), M[k] = max_{j<=k} (z[j] ? j+1 : 0),
// z[j] = (j < NTOK && seq[j]==0).
__global__ void scan_kernel(const int* __restrict__ seq, int* __restrict__ segOut) {
    __shared__ int sM[L];
    __shared__ int warpAgg[32];
    int tid = threadIdx.x, lane = tid & 31, wid = tid >> 5;
    int k0 = tid * 3;
    int v0 = (k0     < NTOK && seq[k0]     == 0) ? k0 + 1 : 0;
    int v1 = (k0 + 1 < NTOK && seq[k0 + 1] == 0) ? k0 + 2 : 0;
    int v2 = (k0 + 2 < NTOK && seq[k0 + 2] == 0) ? k0 + 3 : 0;
    int m1 = max(v0, v1), m2 = max(m1, v2);
    int x = m2;
#pragma unroll
    for (int off = 1; off < 32; off <<= 1) {
        int y = __shfl_up_sync(0xffffffffu, x, off);
        if (lane >= off) x = max(x, y);
    }
    if (lane == 31) warpAgg[wid] = x;
    int exw = __shfl_up_sync(0xffffffffu, x, 1);
    if (lane == 0) exw = 0;
    __syncthreads();
    if (wid == 0) {
        int w = warpAgg[lane];
#pragma unroll
        for (int off = 1; off < 32; off <<= 1) {
            int y = __shfl_up_sync(0xffffffffu, w, off);
            if (lane >= off) w = max(w, y);
        }
        int ex = __shfl_up_sync(0xffffffffu, w, 1);
        if (lane == 0) ex = 0;
        warpAgg[lane] = ex;
    }
    __syncthreads();
    int base = max(warpAgg[wid], exw);
    sM[k0]     = max(base, v0);
    sM[k0 + 1] = max(base, m1);
    sM[k0 + 2] = max(base, m2);
    __syncthreads();
    if (tid == 0) segOut[0] = 0;
#pragma unroll
    for (int u = 1; u <= 3; ++u) {
        int i = k0 + u;
        if (i < L) segOut[i] = max(1, sM[i - 1]);
    }
}

// ---------------- tensor-core GEMM: C[M,N] = (Ah+Al)[M,512] @ Bh[N,512]^T + bias ----------------
// fp16 2-term: C ~= Ah*Bh + Al*Bh, fp32 accumulate.
// Block tile 128x64, 8 warps (4m x 2n), BK=32, 2-stage cp.async pipeline, 80B smem rows.
#define SA_PLANE 10240
#define A_STAGE  20480
#define SB_BASE  40960
#define SB_STAGE 5120
#define SMEM_TOT 51200

__global__ __launch_bounds__(256) void gemm_f16_kernel(
    const f16* __restrict__ Ah, const f16* __restrict__ Al,
    const f16* __restrict__ Wh,
    const float* __restrict__ bias,
    float* __restrict__ outF,
    f16* __restrict__ outHi, f16* __restrict__ outLo,
    int act, int ldc)
{
    extern __shared__ __align__(16) unsigned char smem_raw[];
    const uint32_t sbase = (uint32_t)__cvta_generic_to_shared(smem_raw);
    const int tid = threadIdx.x;
    const int lane = tid & 31, wid = tid >> 5;
    const int bm = blockIdx.y * 128, bn = blockIdx.x * 64;
    const int warp_m = wid >> 1, warp_n = wid & 1;

    const int lr  = tid >> 2;
    const int lcB = (tid & 3) * 16;
    const int lcG = (tid & 3) * 8;

    const int a_off = (warp_m * 32 + (lane & 7) + ((lane >> 3) & 1) * 8) * 80
                    + ((lane >> 4) & 1) * 16;
    const int b_off = (warp_n * 32 + (lane & 7) + ((lane >> 4) & 1) * 8) * 80
                    + ((lane >> 3) & 1) * 16;

    const f16* gAh0 = Ah + (size_t)(bm + lr) * Dm + lcG;
    const f16* gAl0 = Al + (size_t)(bm + lr) * Dm + lcG;
    const f16* gBh0 = Wh + (size_t)(bn + lr) * Dm + lcG;

    float acc[2][4][4];
#pragma unroll
    for (int mt = 0; mt < 2; ++mt)
#pragma unroll
        for (int nt = 0; nt < 4; ++nt)
#pragma unroll
            for (int u = 0; u < 4; ++u) acc[mt][nt][u] = 0.f;

#define LOADSTAGE(s, k0) do {                                              \
        uint32_t dA = sbase + (s) * A_STAGE + lr * 80 + lcB;               \
        cp16(dA,                      gAh0 + (k0));                        \
        cp16(dA + SA_PLANE,           gAl0 + (k0));                        \
        cp16(dA + 64 * 80,            gAh0 + 64 * Dm + (k0));              \
        cp16(dA + 64 * 80 + SA_PLANE, gAl0 + 64 * Dm + (k0));              \
        uint32_t dB = sbase + SB_BASE + (s) * SB_STAGE + lr * 80 + lcB;    \
        cp16(dB, gBh0 + (k0));                                             \
        asm volatile("cp.async.commit_group;\n" ::);                       \
    } while (0)

    LOADSTAGE(0, 0);

    for (int kt = 0; kt < 16; ++kt) {
        if (kt < 15) {
            LOADSTAGE((kt + 1) & 1, (kt + 1) * 32);
            asm volatile("cp.async.wait_group 1;\n" ::);
        } else {
            asm volatile("cp.async.wait_group 0;\n" ::);
        }
        __syncthreads();

        const int s = kt & 1;
        const uint32_t sA0 = sbase + s * A_STAGE + a_off;
        const uint32_t sB0 = sbase + SB_BASE + s * SB_STAGE + b_off;
#pragma unroll
        for (int ks = 0; ks < 2; ++ks) {
            uint32_t ah[2][4], al[2][4], bh[2][4];
#pragma unroll
            for (int mt = 0; mt < 2; ++mt) {
                uint32_t ad = sA0 + mt * 16 * 80 + ks * 32;
                ldsm4(ah[mt], ad);
                ldsm4(al[mt], ad + SA_PLANE);
            }
#pragma unroll
            for (int ng = 0; ng < 2; ++ng) {
                uint32_t bd = sB0 + ng * 16 * 80 + ks * 32;
                ldsm4(bh[ng], bd);
            }
#pragma unroll
            for (int mt = 0; mt < 2; ++mt)
#pragma unroll
                for (int nt = 0; nt < 4; ++nt) {
                    const int ng = nt >> 1, hb = (nt & 1) * 2;
                    mma_f16(acc[mt][nt], ah[mt], bh[ng][hb], bh[ng][hb + 1]);
                    mma_f16(acc[mt][nt], al[mt], bh[ng][hb], bh[ng][hb + 1]);
                }
        }
        __syncthreads();
    }
#undef LOADSTAGE

    const int gid = lane >> 2, tig = lane & 3;
#pragma unroll
    for (int mt = 0; mt < 2; ++mt)
#pragma unroll
        for (int nt = 0; nt < 4; ++nt) {
            int row = bm + warp_m * 32 + mt * 16 + gid;
            int col = bn + warp_n * 32 + nt * 8 + tig * 2;
            float b0 = bias[col], b1 = bias[col + 1];
            float r0 = acc[mt][nt][0] + b0;
            float r1 = acc[mt][nt][1] + b1;
            float r2 = acc[mt][nt][2] + b0;
            float r3 = acc[mt][nt][3] + b1;
            if (act) {
                r0 = r0 > 0.f ? r0 : 0.01f * r0;
                r1 = r1 > 0.f ? r1 : 0.01f * r1;
                r2 = r2 > 0.f ? r2 : 0.01f * r2;
                r3 = r3 > 0.f ? r3 : 0.01f * r3;
            }
            if (outF) {
                *(float2*)(outF + (size_t)row * ldc + col)       = make_float2(r0, r1);
                *(float2*)(outF + (size_t)(row + 8) * ldc + col) = make_float2(r2, r3);
            }
            if (outHi) {
                f16 h0, l0, h1, l1, h2, l2, h3, l3;
                split_f16(r0, h0, l0); split_f16(r1, h1, l1);
                split_f16(r2, h2, l2); split_f16(r3, h3, l3);
                __half2 t;
                t.x = h0; t.y = h1;
                *(__half2*)(outHi + (size_t)row * ldc + col) = t;
                t.x = l0; t.y = l1;
                *(__half2*)(outLo + (size_t)row * ldc + col) = t;
                t.x = h2; t.y = h3;
                *(__half2*)(outHi + (size_t)(row + 8) * ldc + col) = t;
                t.x = l2; t.y = l3;
                *(__half2*)(outLo + (size_t)(row + 8) * ldc + col) = t;
            }
        }
}

// ---------------- sparse masked attention (proven r3 structure, fp16 outputs) ----------------
__global__ __launch_bounds__(256) void attn_kernel(
    const float* __restrict__ QKV, const int* __restrict__ seg,
    f16* __restrict__ Oh, f16* __restrict__ Ol) {
    int i = blockIdx.x;
    int h = threadIdx.x >> 5;
    int lane = threadIdx.x & 31;
    __shared__ float qs[Dm];

    for (int c = threadIdx.x; c < Dm; c += 256)
        qs[c] = QKV[(size_t)i * 1536 + c];
    __syncthreads();

    const float* Kbase = QKV + Dm;
    const float* Vbase = QKV + 2 * Dm;
    const float4* qh4 = (const float4*)(qs + h * DHd);

    int s = seg[i];
    int n = 1 + max(0, i - s);

    float m = -1e30f, l = 0.f;
    float2 oacc = make_float2(0.f, 0.f);

    for (int base = 0; base < n; base += 32) {
        int t = base + lane;
        bool valid = t < n;
        int j = (t == 0) ? 0 : s + t - 1;
        float sc = -1e30f;
        if (valid) {
            const float4* kr = (const float4*)(Kbase + (size_t)j * 1536 + h * DHd);
            float a0 = 0.f, a1 = 0.f;
#pragma unroll
            for (int d4 = 0; d4 < 16; d4 += 2) {
                float4 k0 = kr[d4],     q0 = qh4[d4];
                float4 k1 = kr[d4 + 1], q1 = qh4[d4 + 1];
                a0 += q0.x * k0.x + q0.y * k0.y + q0.z * k0.z + q0.w * k0.w;
                a1 += q1.x * k1.x + q1.y * k1.y + q1.z * k1.z + q1.w * k1.w;
            }
            sc = (a0 + a1) * 0.125f;
        }
        float cm = sc;
#pragma unroll
        for (int off = 16; off; off >>= 1)
            cm = fmaxf(cm, __shfl_xor_sync(0xffffffffu, cm, off));
        float nm = fmaxf(m, cm);
        float scale = __expf(m - nm);
        float w = valid ? __expf(sc - nm) : 0.f;
        float ws = w;
#pragma unroll
        for (int off = 16; off; off >>= 1)
            ws += __shfl_xor_sync(0xffffffffu, ws, off);
        l = l * scale + ws;
        oacc.x *= scale; oacc.y *= scale;

        int cnt = min(32, n - base);
        const float* vcol = Vbase + h * DHd + lane * 2;
        for (int t2 = 0; t2 < cnt; ++t2) {
            float wj = __shfl_sync(0xffffffffu, w, t2);
            int jj   = __shfl_sync(0xffffffffu, j, t2);
            float2 v2 = *(const float2*)(vcol + (size_t)jj * 1536);
            oacc.x += wj * v2.x;
            oacc.y += wj * v2.y;
        }
        m = nm;
    }

    float inv = 1.f / l;
    float ox = oacc.x * inv, oy = oacc.y * inv;
    f16 hx, lx, hy, ly;
    split_f16(ox, hx, lx); split_f16(oy, hy, ly);
    int col = h * DHd + lane * 2;
    __half2 t2o;
    t2o.x = hx; t2o.y = hy;
    *(__half2*)(Oh + (size_t)i * Dm + col) = t2o;
    t2o.x = lx; t2o.y = ly;
    *(__half2*)(Ol + (size_t)i * Dm + col) = t2o;
}

// ---------------- layernorm (optional residual), fp32/fp16-plane outputs ----------------
__global__ __launch_bounds__(128) void ln_kernel(
    const float* __restrict__ X, const float* __restrict__ Y,
    const float* __restrict__ g, const float* __restrict__ b,
    float* __restrict__ outF, f16* __restrict__ outHi, f16* __restrict__ outLo) {
    int row = blockIdx.x;
    int tid = threadIdx.x;
    __shared__ float red[4];
    float v[4];
    float s = 0.f;
#pragma unroll
    for (int u = 0; u < 4; ++u) {
        int c = tid + u * 128;
        float t = X[(size_t)row * Dm + c];
        if (Y) t += Y[(size_t)row * Dm + c];
        v[u] = t; s += t;
    }
#pragma unroll
    for (int off = 16; off; off >>= 1) s += __shfl_xor_sync(0xffffffffu, s, off);
    if ((tid & 31) == 0) red[tid >> 5] = s;
    __syncthreads();
    float mean = (red[0] + red[1] + red[2] + red[3]) * (1.f / 512.f);
    float s2 = 0.f;
#pragma unroll
    for (int u = 0; u < 4; ++u) { float d = v[u] - mean; s2 += d * d; }
#pragma unroll
    for (int off = 16; off; off >>= 1) s2 += __shfl_xor_sync(0xffffffffu, s2, off);
    __syncthreads();
    if ((tid & 31) == 0) red[tid >> 5] = s2;
    __syncthreads();
    float var = (red[0] + red[1] + red[2] + red[3]) * (1.f / 512.f);
    float inv = rsqrtf(var + 1e-5f);
#pragma unroll
    for (int u = 0; u < 4; ++u) {
        int c = tid + u * 128;
        float r = (v[u] - mean) * inv * g[c] + b[c];
        if (outF) outF[(size_t)row * Dm + c] = r;
        if (outHi) {
            f16 h, lo2; split_f16(r, h, lo2);
            outHi[(size_t)row * Dm + c] = h;
            outLo[(size_t)row * Dm + c] = lo2;
        }
    }
}

// ---------------- orchestration ----------------
extern "C" void kernel_launch(void* const* d_in, const int* in_sizes, int n_in,
                              void* d_out, int out_size) {
    const int*   idx = (const int*)d_in[0];
    const int*   seq = (const int*)d_in[1];
    const float* Wt  = (const float*)d_in[2];
    const float* bt  = (const float*)d_in[3];
    const float* Wa  = (const float*)d_in[4];
    const float* ba  = (const float*)d_in[5];
    const float* Wm  = (const float*)d_in[6];
    const float* bm  = (const float*)d_in[7];
    const float* sos = (const float*)d_in[8];
    const float* Wq  = (const float*)d_in[9];
    const float* bq  = (const float*)d_in[10];
    const float* Wk  = (const float*)d_in[11];
    const float* bk  = (const float*)d_in[12];
    const float* Wv  = (const float*)d_in[13];
    const float* bv  = (const float*)d_in[14];
    const float* Wo  = (const float*)d_in[15];
    const float* bo  = (const float*)d_in[16];
    const float* W1  = (const float*)d_in[17];
    const float* b1  = (const float*)d_in[18];
    const float* W2  = (const float*)d_in[19];
    const float* b2  = (const float*)d_in[20];
    const float* g1  = (const float*)d_in[21];
    const float* be1 = (const float*)d_in[22];
    const float* g2  = (const float*)d_in[23];
    const float* be2 = (const float*)d_in[24];
    float* out = (float*)d_out;

    float *qkv, *a, *xa, *y, *bqkv; int* seg;
    f16 *xh, *xl, *oh, *ol, *xah, *xal, *hh, *hl, *Wbh;
    cudaGetSymbolAddress((void**)&qkv, g_qkv);
    cudaGetSymbolAddress((void**)&a,   g_a);
    cudaGetSymbolAddress((void**)&xa,  g_xa);
    cudaGetSymbolAddress((void**)&y,   g_y);
    cudaGetSymbolAddress((void**)&bqkv, g_bqkv);
    cudaGetSymbolAddress((void**)&seg, g_seg);
    cudaGetSymbolAddress((void**)&xh,  g_xh);
    cudaGetSymbolAddress((void**)&xl,  g_xl);
    cudaGetSymbolAddress((void**)&oh,  g_oh);
    cudaGetSymbolAddress((void**)&ol,  g_ol);
    cudaGetSymbolAddress((void**)&xah, g_xah);
    cudaGetSymbolAddress((void**)&xal, g_xal);
    cudaGetSymbolAddress((void**)&hh,  g_hh);
    cudaGetSymbolAddress((void**)&hl,  g_hl);
    cudaGetSymbolAddress((void**)&Wbh, g_Wh);

    cudaFuncSetAttribute(gemm_f16_kernel,
                         cudaFuncAttributeMaxDynamicSharedMemorySize, SMEM_TOT);

    const size_t WSZ = (size_t)Dm * Dm;
    const int n4 = (int)WSZ / 4;
    dim3 cg(n4 / 256, 6);
    conv6_kernel<<<cg, 256>>>(Wq, Wk, Wv, Wo, W1, W2, Wbh);      // launch 1
    biascat_kernel<<<6, 256>>>(bq, bk, bv, bqkv);                // launch 2
    embed_kernel<<<(L * Dm + 255) / 256, 256>>>(idx, Wt, bt, Wa, ba, Wm, bm, sos, xh, xl); // 3
    scan_kernel<<<1, 1024>>>(seq, seg);                          // launch 4

    dim3 ggQKV(3 * Dm / 64, L / 128);   // (24, 24)
    dim3 gg(Dm / 64, L / 128);          // (8, 24)
    for (int layer = 0; layer < 2; ++layer) {
        f16* Woh = Wbh + 3 * WSZ;
        f16* W1h = Wbh + 4 * WSZ;
        f16* W2h = Wbh + 5 * WSZ;

        gemm_f16_kernel<<<ggQKV, 256, SMEM_TOT>>>(xh, xl, Wbh, bqkv,
                                                  qkv, nullptr, nullptr, 0, 1536); // launch 5
        attn_kernel<<<L, 256>>>(qkv, seg, oh, ol);                                 // launch 6 (profiled)
        gemm_f16_kernel<<<gg, 256, SMEM_TOT>>>(oh, ol, Woh, bo,
                                               a, nullptr, nullptr, 0, Dm);
        ln_kernel<<<L, 128>>>(a, nullptr, g1, be1, xa, xah, xal);
        gemm_f16_kernel<<<gg, 256, SMEM_TOT>>>(xah, xal, W1h, b1,
                                               nullptr, hh, hl, 1, Dm);
        gemm_f16_kernel<<<gg, 256, SMEM_TOT>>>(hh, hl, W2h, b2,
                                               y, nullptr, nullptr, 0, Dm);
        if (layer == 0)
            ln_kernel<<<L, 128>>>(xa, y, g2, be2, nullptr, xh, xl);
        else
            ln_kernel<<<L, 128>>>(xa, y, g2, be2, out, nullptr, nullptr);
    }
}

// round 7
// speedup vs baseline: 1.8789x; 1.0275x over previous
#include <cuda_runtime.h>
#include <cuda_fp16.h>
#include <cstdint>

// ---------------- problem constants ----------------
#define L     3072
#define NTOK  3071
#define Dm    512
#define Hh    8
#define DHd   64
#define T_TYPES 15
#define N_ARGS  73
#define N_MAPS  3

typedef __half f16;

// ---------------- scratch (static device globals; no allocations) ----------------
__device__ float g_qkv[L * 3 * Dm];
__device__ float g_a [L * Dm];
__device__ float g_xa[L * Dm];
__device__ float g_y [L * Dm];
__device__ float g_bqkv[3 * Dm];
__device__ float g_etab[(T_TYPES + N_ARGS + N_MAPS) * Dm];   // 91 x 512
__device__ int   g_seg[L];

// fp16 hi/lo planes for activations; weights hi-only
__device__ f16 g_xh [L * Dm];  __device__ f16 g_xl [L * Dm];
__device__ f16 g_oh [L * Dm];  __device__ f16 g_ol [L * Dm];
__device__ f16 g_xah[L * Dm];  __device__ f16 g_xal[L * Dm];
__device__ f16 g_hh [L * Dm];  __device__ f16 g_hl [L * Dm];
__device__ f16 g_Wh[6 * Dm * Dm];   // Wq,Wk,Wv | Wo | W1 | W2 (hi plane)

// ---------------- helpers ----------------
__device__ __forceinline__ void split_f16(float x, f16& h, f16& l) {
    h = __float2half_rn(x);
    l = __float2half_rn(x - __half2float(h));
}
__device__ __forceinline__ void cp16(uint32_t dst, const void* src) {
    asm volatile("cp.async.cg.shared.global [%0], [%1], 16;\n" :: "r"(dst), "l"(src));
}
__device__ __forceinline__ void ldsm4(uint32_t* r, uint32_t addr) {
    asm volatile("ldmatrix.sync.aligned.m8n8.x4.shared.b16 {%0,%1,%2,%3}, [%4];\n"
                 : "=r"(r[0]), "=r"(r[1]), "=r"(r[2]), "=r"(r[3]) : "r"(addr));
}
__device__ __forceinline__ void mma_f16(float* d, const uint32_t* a, uint32_t b0, uint32_t b1) {
    asm volatile(
        "mma.sync.aligned.m16n8k16.row.col.f32.f16.f16.f32 "
        "{%0,%1,%2,%3}, {%4,%5,%6,%7}, {%8,%9}, {%0,%1,%2,%3};\n"
        : "+f"(d[0]), "+f"(d[1]), "+f"(d[2]), "+f"(d[3])
        : "r"(a[0]), "r"(a[1]), "r"(a[2]), "r"(a[3]), "r"(b0), "r"(b1));
}

// ---------------- weight conversion: all 6 matrices, hi plane only ----------------
__global__ void conv6_kernel(const float* __restrict__ w0, const float* __restrict__ w1,
                             const float* __restrict__ w2, const float* __restrict__ w3,
                             const float* __restrict__ w4, const float* __restrict__ w5,
                             f16* __restrict__ hi) {
    const int n4 = Dm * Dm / 4;
    int i = blockIdx.x * blockDim.x + threadIdx.x;
    if (i >= n4) return;
    int wsel = blockIdx.y;
    const float* in = (wsel == 0) ? w0 : (wsel == 1) ? w1 : (wsel == 2) ? w2
                    : (wsel == 3) ? w3 : (wsel == 4) ? w4 : w5;
    size_t base = (size_t)wsel * Dm * Dm;
    float4 x = ((const float4*)in)[i];
    __half2 p0, p1;
    p0.x = __float2half_rn(x.x); p0.y = __float2half_rn(x.y);
    p1.x = __float2half_rn(x.z); p1.y = __float2half_rn(x.w);
    __half2* H = (__half2*)(hi + base);
    H[i * 2 + 0] = p0;
    H[i * 2 + 1] = p1;
}

// ---------------- pretab: embedding tables (91x512) + fused QKV bias concat ----------------
#define ETAB_N ((T_TYPES + N_ARGS + N_MAPS) * Dm)   // 46592
__global__ void pretab_kernel(const float* __restrict__ Wt, const float* __restrict__ bt,
                              const float* __restrict__ Wa, const float* __restrict__ ba,
                              const float* __restrict__ Wm, const float* __restrict__ bm,
                              const float* __restrict__ bq, const float* __restrict__ bk,
                              const float* __restrict__ bv,
                              float* __restrict__ Et, float* __restrict__ bqkv) {
    int i = blockIdx.x * blockDim.x + threadIdx.x;
    if (i < ETAB_N) {
        int r = i >> 9, d = i & 511;
        float v;
        if (r < T_TYPES)               v = Wt[d * T_TYPES + r] + bt[d];
        else if (r < T_TYPES + N_ARGS) v = Wa[d * N_ARGS + (r - T_TYPES)] + ba[d];
        else                           v = Wm[d * N_MAPS + (r - T_TYPES - N_ARGS)] + bm[d];
        Et[i] = v;
    } else {
        int j = i - ETAB_N;
        if (j < 3 * Dm) {
            const float* src = (j < Dm) ? bq : (j < 2 * Dm) ? bk : bv;
            bqkv[j] = src[j & (Dm - 1)];
        }
    }
}

// ---------------- embedding: coalesced table-row sums -> fp16 hi/lo planes ----------------
__global__ __launch_bounds__(128) void embed_kernel(const int* __restrict__ idx,
                              const float* __restrict__ Et, const float* __restrict__ sos,
                              f16* __restrict__ Xh, f16* __restrict__ Xl) {
    int n = blockIdx.x;
    int tid = threadIdx.x;
    int c = tid * 4;
    float4 v;
    if (n == 0) {
        v = *(const float4*)(sos + c);
    } else {
        int id = idx[n - 1];
        int t = id / (N_ARGS * N_MAPS);
        int a = (id / N_MAPS) % N_ARGS;
        int m = id % N_MAPS;
        float4 vt = *(const float4*)(Et + (size_t)t * Dm + c);
        float4 va = *(const float4*)(Et + (size_t)(T_TYPES + a) * Dm + c);
        float4 vm = *(const float4*)(Et + (size_t)(T_TYPES + N_ARGS + m) * Dm + c);
        v.x = vt.x + va.x + vm.x;
        v.y = vt.y + va.y + vm.y;
        v.z = vt.z + va.z + vm.z;
        v.w = vt.w + va.w + vm.w;
    }
    f16 h0, l0, h1, l1, h2, l2, h3, l3;
    split_f16(v.x, h0, l0); split_f16(v.y, h1, l1);
    split_f16(v.z, h2, l2); split_f16(v.w, h3, l3);
    __half2 t2;
    t2.x = h0; t2.y = h1; *(__half2*)(Xh + (size_t)n * Dm + c) = t2;
    t2.x = h2; t2.y = h3; *(__half2*)(Xh + (size_t)n * Dm + c + 2) = t2;
    t2.x = l0; t2.y = l1; *(__half2*)(Xl + (size_t)n * Dm + c) = t2;
    t2.x = l2; t2.y = l3; *(__half2*)(Xl + (size_t)n * Dm + c + 2) = t2;
}

// ---------------- scan: block max-scan for per-row segment start ----------------
__global__ void scan_kernel(const int* __restrict__ seq, int* __restrict__ segOut) {
    __shared__ int sM[L];
    __shared__ int warpAgg[32];
    int tid = threadIdx.x, lane = tid & 31, wid = tid >> 5;
    int k0 = tid * 3;
    int v0 = (k0     < NTOK && seq[k0]     == 0) ? k0 + 1 : 0;
    int v1 = (k0 + 1 < NTOK && seq[k0 + 1] == 0) ? k0 + 2 : 0;
    int v2 = (k0 + 2 < NTOK && seq[k0 + 2] == 0) ? k0 + 3 : 0;
    int m1 = max(v0, v1), m2 = max(m1, v2);
    int x = m2;
#pragma unroll
    for (int off = 1; off < 32; off <<= 1) {
        int y = __shfl_up_sync(0xffffffffu, x, off);
        if (lane >= off) x = max(x, y);
    }
    if (lane == 31) warpAgg[wid] = x;
    int exw = __shfl_up_sync(0xffffffffu, x, 1);
    if (lane == 0) exw = 0;
    __syncthreads();
    if (wid == 0) {
        int w = warpAgg[lane];
#pragma unroll
        for (int off = 1; off < 32; off <<= 1) {
            int y = __shfl_up_sync(0xffffffffu, w, off);
            if (lane >= off) w = max(w, y);
        }
        int ex = __shfl_up_sync(0xffffffffu, w, 1);
        if (lane == 0) ex = 0;
        warpAgg[lane] = ex;
    }
    __syncthreads();
    int base = max(warpAgg[wid], exw);
    sM[k0]     = max(base, v0);
    sM[k0 + 1] = max(base, m1);
    sM[k0 + 2] = max(base, m2);
    __syncthreads();
    if (tid == 0) segOut[0] = 0;
#pragma unroll
    for (int u = 1; u <= 3; ++u) {
        int i = k0 + u;
        if (i < L) segOut[i] = max(1, sM[i - 1]);
    }
}

// ---------------- tensor-core GEMM: C = (Ah+Al) @ Bh^T + bias ----------------
// 64x64 tiles, 128 threads (4 warps 2m x 2n, warp tile 32x32), BK=32,
// 3-stage cp.async, one __syncthreads per K-step. 80B smem rows.
#define STG_A    5120                 // one 64x32-f16 plane at 80B stride
#define STG_BYTES (3 * STG_A)         // Ah | Al | Bh
#define SMEM_TOT (3 * STG_BYTES)      // 46080

__global__ __launch_bounds__(128) void gemm_f16_kernel(
    const f16* __restrict__ Ah, const f16* __restrict__ Al,
    const f16* __restrict__ Wh,
    const float* __restrict__ bias,
    float* __restrict__ outF,
    f16* __restrict__ outHi, f16* __restrict__ outLo,
    int act, int ldc)
{
    extern __shared__ __align__(16) unsigned char smem_raw[];
    const uint32_t sbase = (uint32_t)__cvta_generic_to_shared(smem_raw);
    const int tid = threadIdx.x;
    const int lane = tid & 31, wid = tid >> 5;
    const int bm = blockIdx.y * 64, bn = blockIdx.x * 64;
    const int warp_m = wid >> 1, warp_n = wid & 1;

    // loads: 2 threads per row, each 2x16B per plane
    const int lr = tid >> 1;               // row 0..63
    const int lhalf = tid & 1;             // chunk pair
    const uint32_t sOff = (uint32_t)lr * 80 + lhalf * 32;

    const int a_off = (warp_m * 32 + (lane & 7) + ((lane >> 3) & 1) * 8) * 80
                    + ((lane >> 4) & 1) * 16;
    const int b_off = (warp_n * 32 + (lane & 7) + ((lane >> 4) & 1) * 8) * 80
                    + ((lane >> 3) & 1) * 16;

    const f16* gAh0 = Ah + (size_t)(bm + lr) * Dm + lhalf * 16;
    const f16* gAl0 = Al + (size_t)(bm + lr) * Dm + lhalf * 16;
    const f16* gBh0 = Wh + (size_t)(bn + lr) * Dm + lhalf * 16;

    float acc[2][4][4];
#pragma unroll
    for (int mt = 0; mt < 2; ++mt)
#pragma unroll
        for (int nt = 0; nt < 4; ++nt)
#pragma unroll
            for (int u = 0; u < 4; ++u) acc[mt][nt][u] = 0.f;

#define LOADSTAGE(s, k0) do {                                   \
        uint32_t d0 = sbase + (s) * STG_BYTES + sOff;           \
        cp16(d0,                  gAh0 + (k0));                 \
        cp16(d0 + 16,             gAh0 + (k0) + 8);             \
        cp16(d0 + STG_A,          gAl0 + (k0));                 \
        cp16(d0 + STG_A + 16,     gAl0 + (k0) + 8);             \
        cp16(d0 + 2 * STG_A,      gBh0 + (k0));                 \
        cp16(d0 + 2 * STG_A + 16, gBh0 + (k0) + 8);             \
        asm volatile("cp.async.commit_group;\n" ::);            \
    } while (0)

    LOADSTAGE(0, 0);
    LOADSTAGE(1, 32);

    int sCur = 0, sNxt = 2;   // compute stage; next load stage
    for (int kt = 0; kt < 16; ++kt) {
        if (kt < 15)
            asm volatile("cp.async.wait_group 1;\n" ::);
        else
            asm volatile("cp.async.wait_group 0;\n" ::);
        __syncthreads();

        const uint32_t sA0 = sbase + sCur * STG_BYTES + a_off;
        const uint32_t sB0 = sbase + sCur * STG_BYTES + 2 * STG_A + b_off;
#pragma unroll
        for (int ks = 0; ks < 2; ++ks) {
            uint32_t ah[2][4], al[2][4], bh[2][4];
#pragma unroll
            for (int mt = 0; mt < 2; ++mt) {
                uint32_t ad = sA0 + mt * 16 * 80 + ks * 32;
                ldsm4(ah[mt], ad);
                ldsm4(al[mt], ad + STG_A);
            }
#pragma unroll
            for (int ng = 0; ng < 2; ++ng) {
                uint32_t bd = sB0 + ng * 16 * 80 + ks * 32;
                ldsm4(bh[ng], bd);
            }
#pragma unroll
            for (int mt = 0; mt < 2; ++mt)
#pragma unroll
                for (int nt = 0; nt < 4; ++nt) {
                    const int ng = nt >> 1, hb = (nt & 1) * 2;
                    mma_f16(acc[mt][nt], ah[mt], bh[ng][hb], bh[ng][hb + 1]);
                    mma_f16(acc[mt][nt], al[mt], bh[ng][hb], bh[ng][hb + 1]);
                }
        }
        if (kt < 14)
            LOADSTAGE(sNxt, (kt + 2) * 32);
        sCur = (sCur == 2) ? 0 : sCur + 1;
        sNxt = (sNxt == 2) ? 0 : sNxt + 1;
    }
#undef LOADSTAGE

    const int gid = lane >> 2, tig = lane & 3;
#pragma unroll
    for (int mt = 0; mt < 2; ++mt)
#pragma unroll
        for (int nt = 0; nt < 4; ++nt) {
            int row = bm + warp_m * 32 + mt * 16 + gid;
            int col = bn + warp_n * 32 + nt * 8 + tig * 2;
            float b0 = bias[col], b1 = bias[col + 1];
            float r0 = acc[mt][nt][0] + b0;
            float r1 = acc[mt][nt][1] + b1;
            float r2 = acc[mt][nt][2] + b0;
            float r3 = acc[mt][nt][3] + b1;
            if (act) {
                r0 = r0 > 0.f ? r0 : 0.01f * r0;
                r1 = r1 > 0.f ? r1 : 0.01f * r1;
                r2 = r2 > 0.f ? r2 : 0.01f * r2;
                r3 = r3 > 0.f ? r3 : 0.01f * r3;
            }
            if (outF) {
                *(float2*)(outF + (size_t)row * ldc + col)       = make_float2(r0, r1);
                *(float2*)(outF + (size_t)(row + 8) * ldc + col) = make_float2(r2, r3);
            }
            if (outHi) {
                f16 h0, l0, h1, l1, h2, l2, h3, l3;
                split_f16(r0, h0, l0); split_f16(r1, h1, l1);
                split_f16(r2, h2, l2); split_f16(r3, h3, l3);
                __half2 t;
                t.x = h0; t.y = h1;
                *(__half2*)(outHi + (size_t)row * ldc + col) = t;
                t.x = l0; t.y = l1;
                *(__half2*)(outLo + (size_t)row * ldc + col) = t;
                t.x = h2; t.y = h3;
                *(__half2*)(outHi + (size_t)(row + 8) * ldc + col) = t;
                t.x = l2; t.y = l3;
                *(__half2*)(outLo + (size_t)(row + 8) * ldc + col) = t;
            }
        }
}

// ---------------- sparse masked attention (proven structure) ----------------
__global__ __launch_bounds__(256) void attn_kernel(
    const float* __restrict__ QKV, const int* __restrict__ seg,
    f16* __restrict__ Oh, f16* __restrict__ Ol) {
    int i = blockIdx.x;
    int h = threadIdx.x >> 5;
    int lane = threadIdx.x & 31;
    __shared__ float qs[Dm];

    for (int c = threadIdx.x; c < Dm; c += 256)
        qs[c] = QKV[(size_t)i * 1536 + c];
    __syncthreads();

    const float* Kbase = QKV + Dm;
    const float* Vbase = QKV + 2 * Dm;
    const float4* qh4 = (const float4*)(qs + h * DHd);

    int s = seg[i];
    int n = 1 + max(0, i - s);

    float m = -1e30f, l = 0.f;
    float2 oacc = make_float2(0.f, 0.f);

    for (int base = 0; base < n; base += 32) {
        int t = base + lane;
        bool valid = t < n;
        int j = (t == 0) ? 0 : s + t - 1;
        float sc = -1e30f;
        if (valid) {
            const float4* kr = (const float4*)(Kbase + (size_t)j * 1536 + h * DHd);
            float a0 = 0.f, a1 = 0.f;
#pragma unroll
            for (int d4 = 0; d4 < 16; d4 += 2) {
                float4 k0 = kr[d4],     q0 = qh4[d4];
                float4 k1 = kr[d4 + 1], q1 = qh4[d4 + 1];
                a0 += q0.x * k0.x + q0.y * k0.y + q0.z * k0.z + q0.w * k0.w;
                a1 += q1.x * k1.x + q1.y * k1.y + q1.z * k1.z + q1.w * k1.w;
            }
            sc = (a0 + a1) * 0.125f;
        }
        float cm = sc;
#pragma unroll
        for (int off = 16; off; off >>= 1)
            cm = fmaxf(cm, __shfl_xor_sync(0xffffffffu, cm, off));
        float nm = fmaxf(m, cm);
        float scale = __expf(m - nm);
        float w = valid ? __expf(sc - nm) : 0.f;
        float ws = w;
#pragma unroll
        for (int off = 16; off; off >>= 1)
            ws += __shfl_xor_sync(0xffffffffu, ws, off);
        l = l * scale + ws;
        oacc.x *= scale; oacc.y *= scale;

        int cnt = min(32, n - base);
        const float* vcol = Vbase + h * DHd + lane * 2;
        for (int t2 = 0; t2 < cnt; ++t2) {
            float wj = __shfl_sync(0xffffffffu, w, t2);
            int jj   = __shfl_sync(0xffffffffu, j, t2);
            float2 v2 = *(const float2*)(vcol + (size_t)jj * 1536);
            oacc.x += wj * v2.x;
            oacc.y += wj * v2.y;
        }
        m = nm;
    }

    float inv = 1.f / l;
    float ox = oacc.x * inv, oy = oacc.y * inv;
    f16 hx, lx, hy, ly;
    split_f16(ox, hx, lx); split_f16(oy, hy, ly);
    int col = h * DHd + lane * 2;
    __half2 t2o;
    t2o.x = hx; t2o.y = hy;
    *(__half2*)(Oh + (size_t)i * Dm + col) = t2o;
    t2o.x = lx; t2o.y = ly;
    *(__half2*)(Ol + (size_t)i * Dm + col) = t2o;
}

// ---------------- layernorm (optional residual), fp32/fp16-plane outputs ----------------
__global__ __launch_bounds__(128) void ln_kernel(
    const float* __restrict__ X, const float* __restrict__ Y,
    const float* __restrict__ g, const float* __restrict__ b,
    float* __restrict__ outF, f16* __restrict__ outHi, f16* __restrict__ outLo) {
    int row = blockIdx.x;
    int tid = threadIdx.x;
    __shared__ float red[4];
    float v[4];
    float s = 0.f;
#pragma unroll
    for (int u = 0; u < 4; ++u) {
        int c = tid + u * 128;
        float t = X[(size_t)row * Dm + c];
        if (Y) t += Y[(size_t)row * Dm + c];
        v[u] = t; s += t;
    }
#pragma unroll
    for (int off = 16; off; off >>= 1) s += __shfl_xor_sync(0xffffffffu, s, off);
    if ((tid & 31) == 0) red[tid >> 5] = s;
    __syncthreads();
    float mean = (red[0] + red[1] + red[2] + red[3]) * (1.f / 512.f);
    float s2 = 0.f;
#pragma unroll
    for (int u = 0; u < 4; ++u) { float d = v[u] - mean; s2 += d * d; }
#pragma unroll
    for (int off = 16; off; off >>= 1) s2 += __shfl_xor_sync(0xffffffffu, s2, off);
    __syncthreads();
    if ((tid & 31) == 0) red[tid >> 5] = s2;
    __syncthreads();
    float var = (red[0] + red[1] + red[2] + red[3]) * (1.f / 512.f);
    float inv = rsqrtf(var + 1e-5f);
#pragma unroll
    for (int u = 0; u < 4; ++u) {
        int c = tid + u * 128;
        float r = (v[u] - mean) * inv * g[c] + b[c];
        if (outF) outF[(size_t)row * Dm + c] = r;
        if (outHi) {
            f16 h, lo2; split_f16(r, h, lo2);
            outHi[(size_t)row * Dm + c] = h;
            outLo[(size_t)row * Dm + c] = lo2;
        }
    }
}

// ---------------- orchestration ----------------
extern "C" void kernel_launch(void* const* d_in, const int* in_sizes, int n_in,
                              void* d_out, int out_size) {
    const int*   idx = (const int*)d_in[0];
    const int*   seq = (const int*)d_in[1];
    const float* Wt  = (const float*)d_in[2];
    const float* bt  = (const float*)d_in[3];
    const float* Wa  = (const float*)d_in[4];
    const float* ba  = (const float*)d_in[5];
    const float* Wm  = (const float*)d_in[6];
    const float* bm  = (const float*)d_in[7];
    const float* sos = (const float*)d_in[8];
    const float* Wq  = (const float*)d_in[9];
    const float* bq  = (const float*)d_in[10];
    const float* Wk  = (const float*)d_in[11];
    const float* bk  = (const float*)d_in[12];
    const float* Wv  = (const float*)d_in[13];
    const float* bv  = (const float*)d_in[14];
    const float* Wo  = (const float*)d_in[15];
    const float* bo  = (const float*)d_in[16];
    const float* W1  = (const float*)d_in[17];
    const float* b1  = (const float*)d_in[18];
    const float* W2  = (const float*)d_in[19];
    const float* b2  = (const float*)d_in[20];
    const float* g1  = (const float*)d_in[21];
    const float* be1 = (const float*)d_in[22];
    const float* g2  = (const float*)d_in[23];
    const float* be2 = (const float*)d_in[24];
    float* out = (float*)d_out;

    float *qkv, *a, *xa, *y, *bqkv, *etab; int* seg;
    f16 *xh, *xl, *oh, *ol, *xah, *xal, *hh, *hl, *Wbh;
    cudaGetSymbolAddress((void**)&qkv, g_qkv);
    cudaGetSymbolAddress((void**)&a,   g_a);
    cudaGetSymbolAddress((void**)&xa,  g_xa);
    cudaGetSymbolAddress((void**)&y,   g_y);
    cudaGetSymbolAddress((void**)&bqkv, g_bqkv);
    cudaGetSymbolAddress((void**)&etab, g_etab);
    cudaGetSymbolAddress((void**)&seg, g_seg);
    cudaGetSymbolAddress((void**)&xh,  g_xh);
    cudaGetSymbolAddress((void**)&xl,  g_xl);
    cudaGetSymbolAddress((void**)&oh,  g_oh);
    cudaGetSymbolAddress((void**)&ol,  g_ol);
    cudaGetSymbolAddress((void**)&xah, g_xah);
    cudaGetSymbolAddress((void**)&xal, g_xal);
    cudaGetSymbolAddress((void**)&hh,  g_hh);
    cudaGetSymbolAddress((void**)&hl,  g_hl);
    cudaGetSymbolAddress((void**)&Wbh, g_Wh);

    cudaFuncSetAttribute(gemm_f16_kernel,
                         cudaFuncAttributeMaxDynamicSharedMemorySize, SMEM_TOT);

    const size_t WSZ = (size_t)Dm * Dm;
    const int n4 = (int)WSZ / 4;
    dim3 cg(n4 / 256, 6);
    // launch 1: weight conversion
    conv6_kernel<<<cg, 256>>>(Wq, Wk, Wv, Wo, W1, W2, Wbh);
    // launch 2: embedding tables + qkv bias concat
    pretab_kernel<<<(ETAB_N + 3 * Dm + 255) / 256, 256>>>(Wt, bt, Wa, ba, Wm, bm,
                                                          bq, bk, bv, etab, bqkv);
    // launch 3: embedding
    embed_kernel<<<L, 128>>>(idx, etab, sos, xh, xl);

    dim3 ggQKV(3 * Dm / 64, L / 64);    // (24, 48) = 1152
    dim3 gg(Dm / 64, L / 64);           // (8, 48)  = 384
    for (int layer = 0; layer < 2; ++layer) {
        f16* Woh = Wbh + 3 * WSZ;
        f16* W1h = Wbh + 4 * WSZ;
        f16* W2h = Wbh + 5 * WSZ;

        // launch 4 in iteration 0 (profiled): fused QKV GEMM
        gemm_f16_kernel<<<ggQKV, 128, SMEM_TOT>>>(xh, xl, Wbh, bqkv,
                                                  qkv, nullptr, nullptr, 0, 1536);
        if (layer == 0)
            scan_kernel<<<1, 1024>>>(seq, seg);   // launch 5 (before first attn)
        attn_kernel<<<L, 256>>>(qkv, seg, oh, ol);
        gemm_f16_kernel<<<gg, 128, SMEM_TOT>>>(oh, ol, Woh, bo,
                                               a, nullptr, nullptr, 0, Dm);
        ln_kernel<<<L, 128>>>(a, nullptr, g1, be1, xa, xah, xal);
        gemm_f16_kernel<<<gg, 128, SMEM_TOT>>>(xah, xal, W1h, b1,
                                               nullptr, hh, hl, 1, Dm);
        gemm_f16_kernel<<<gg, 128, SMEM_TOT>>>(hh, hl, W2h, b2,
                                               y, nullptr, nullptr, 0, Dm);
        if (layer == 0)
            ln_kernel<<<L, 128>>>(xa, y, g2, be2, nullptr, xh, xl);
        else
            ln_kernel<<<L, 128>>>(xa, y, g2, be2, out, nullptr, nullptr);
    }
}